// round 10
// baseline (speedup 1.0000x reference)
#include <cuda_runtime.h>
#include <cuda_bf16.h>
#include <cstdint>
#include <cstddef>

// ---------------------------------------------------------------------------
// LatentAttention v7: B=2, T=2048, n_embd=1024, heads=16, latent=64
//   (tcgen05 unavailable: harness targets sm_100, not sm_100a — legacy mma)
//   - GEMMs: bf16x3, cp.async 2-stage, ldmatrix; NO reg cap (spill fix)
//   - flash attention: legacy-mma bf16x3 (byte-identical to v5)
//   - tsplit merged into one launch; 6 launches total so ncu -s5 -c1
//     captures gemm_out_mma.
// ---------------------------------------------------------------------------

#define N_EMBD   1024
#define N_HEADS  16
#define LATENT   64
#define BATCH    2
#define SEQ      2048
#define MROWS    (BATCH * SEQ)          // 4096
#define KDIM     1024

typedef __nv_bfloat16  bf16;
typedef __nv_bfloat162 bf162;

// ------------------------- device scratch ----------------------------------
__device__ float g_Wqc[N_EMBD * N_EMBD];
__device__ float g_bqc[N_EMBD];
__device__ bf16  g_qkvh[3 * MROWS * N_EMBD];    // [qc | k | v] hi
__device__ bf16  g_qkvl[3 * MROWS * N_EMBD];    // lo
__device__ bf16  g_xs_hi[MROWS * N_EMBD];
__device__ bf16  g_xs_lo[MROWS * N_EMBD];
__device__ bf16  g_ys_hi[MROWS * N_EMBD];
__device__ bf16  g_ys_lo[MROWS * N_EMBD];
__device__ bf16  g_wt_hi[4][N_EMBD * N_EMBD];   // 0=Wqc 1=Wk 2=Wv 3=Wo, [N][K]
__device__ bf16  g_wt_lo[4][N_EMBD * N_EMBD];

// ---------------------------------------------------------------------------
__global__ void build_wqc(const float* __restrict__ Wq,
                          const float* __restrict__ Wc,
                          const float* __restrict__ bq,
                          float* __restrict__ Wqc,
                          float* __restrict__ bqc)
{
    int idx = blockIdx.x * blockDim.x + threadIdx.x;
    int c   = idx >> 10;
    int col = idx & 1023;
    int h   = col >> 6;
    int l   = col & 63;
    const float* wrow = &Wq[(size_t)c * N_EMBD + h * LATENT];
    float s = 0.f;
#pragma unroll 8
    for (int d = 0; d < LATENT; d++)
        s += wrow[d] * Wc[d * LATENT + l];
    Wqc[idx] = s;
    if (c == 0) {
        float sb = 0.f;
#pragma unroll 8
        for (int d = 0; d < LATENT; d++)
            sb += bq[h * LATENT + d] * Wc[d * LATENT + l];
        bqc[col] = sb;
    }
}

__global__ void split2(const float* __restrict__ src,
                       bf162* __restrict__ hi, bf162* __restrict__ lo, int n2)
{
    int i = blockIdx.x * blockDim.x + threadIdx.x;
    if (i >= n2) return;
    const float2 v = reinterpret_cast<const float2*>(src)[i];
    bf16 h0 = __float2bfloat16(v.x);
    bf16 h1 = __float2bfloat16(v.y);
    bf16 l0 = __float2bfloat16(v.x - __bfloat162float(h0));
    bf16 l1 = __float2bfloat16(v.y - __bfloat162float(h1));
    hi[i] = bf162(h0, h1);
    lo[i] = bf162(l0, l1);
}

// transpose + split all 4 weight matrices in one launch (grid.z selects)
__global__ void tsplit_all(const float* __restrict__ W0,
                           const float* __restrict__ W1,
                           const float* __restrict__ W2,
                           const float* __restrict__ W3,
                           bf16* __restrict__ Th, bf16* __restrict__ Tl)
{
    __shared__ float t[32][33];
    const int z = blockIdx.z;
    const float* W = (z == 0) ? W0 : (z == 1) ? W1 : (z == 2) ? W2 : W3;
    bf16* th = Th + (size_t)z * N_EMBD * N_EMBD;
    bf16* tl = Tl + (size_t)z * N_EMBD * N_EMBD;

    const int tx = threadIdx.x, ty = threadIdx.y;
    const int n0 = blockIdx.x * 32, k0 = blockIdx.y * 32;
#pragma unroll
    for (int i = 0; i < 4; i++)
        t[ty + 8 * i][tx] = W[(size_t)(k0 + ty + 8 * i) * N_EMBD + n0 + tx];
    __syncthreads();
#pragma unroll
    for (int i = 0; i < 4; i++) {
        const int n = n0 + ty + 8 * i;
        const int k = k0 + tx;
        const float v = t[tx][ty + 8 * i];
        bf16 h = __float2bfloat16(v);
        bf16 l = __float2bfloat16(v - __bfloat162float(h));
        th[(size_t)n * KDIM + k] = h;
        tl[(size_t)n * KDIM + k] = l;
    }
}

// ---------------------------------------------------------------------------
// primitives
// ---------------------------------------------------------------------------
__device__ __forceinline__
void mma_bf16(float& d0, float& d1, float& d2, float& d3,
              uint32_t a0, uint32_t a1, uint32_t a2, uint32_t a3,
              uint32_t b0, uint32_t b1)
{
    asm volatile(
        "mma.sync.aligned.m16n8k16.row.col.f32.bf16.bf16.f32 "
        "{%0,%1,%2,%3}, {%4,%5,%6,%7}, {%8,%9}, {%0,%1,%2,%3};\n"
        : "+f"(d0), "+f"(d1), "+f"(d2), "+f"(d3)
        : "r"(a0), "r"(a1), "r"(a2), "r"(a3), "r"(b0), "r"(b1));
}

__device__ __forceinline__
void split_pack(float x, float y, uint32_t& hi, uint32_t& lo)
{
    bf162 h = __floats2bfloat162_rn(x, y);
    bf162 l = __floats2bfloat162_rn(x - __bfloat162float(h.x),
                                    y - __bfloat162float(h.y));
    hi = *reinterpret_cast<uint32_t*>(&h);
    lo = *reinterpret_cast<uint32_t*>(&l);
}

__device__ __forceinline__ void cp16(uint32_t d, const void* s) {
    asm volatile("cp.async.cg.shared.global [%0], [%1], 16;" :: "r"(d), "l"(s));
}
__device__ __forceinline__ void cp_commit() {
    asm volatile("cp.async.commit_group;");
}
__device__ __forceinline__ void cp_wait1() {
    asm volatile("cp.async.wait_group 1;");
}
__device__ __forceinline__
void ldsm4(uint32_t& r0, uint32_t& r1, uint32_t& r2, uint32_t& r3, uint32_t a) {
    asm volatile("ldmatrix.sync.aligned.m8n8.x4.shared.b16 {%0,%1,%2,%3}, [%4];"
                 : "=r"(r0), "=r"(r1), "=r"(r2), "=r"(r3) : "r"(a));
}

// ---------------------------------------------------------------------------
// GEMM bf16x3: 128x128 tile, BK=32, 8 warps (2m x 4n), cp.async 2-stage,
// ldmatrix fragment loads.  NO min-blocks bound -> no forced 128-reg cap.
// ---------------------------------------------------------------------------
#define SMW 20
#define GST (128 * SMW)            // words per array per stage
#define GSTAGE (4 * GST)           // words per stage
#define GEMM_SMEM (2 * GSTAGE * 4) // 81920 bytes

template<bool SPLIT_OUT>
__device__ __forceinline__
void gemm3_body(const bf16* __restrict__ Ah_, const bf16* __restrict__ Al_,
                const bf16* __restrict__ Bh_, const bf16* __restrict__ Bl_,
                const float* __restrict__ bias,
                float* __restrict__ C, bf16* __restrict__ Ch, bf16* __restrict__ Cl,
                int N, int K, int bx, int by)
{
    extern __shared__ uint32_t gsm[];
    const int tid    = threadIdx.x;
    const int lane   = tid & 31;
    const int wid    = tid >> 5;
    const int warp_m = wid >> 2;
    const int warp_n = wid & 3;
    const int m0     = by * 128;
    const int n0     = bx * 128;
    const int lg     = lane >> 2;
    const int lc     = lane & 3;
    const uint32_t sbase = (uint32_t)__cvta_generic_to_shared(gsm);

    float acc[4][4][4];
#pragma unroll
    for (int i = 0; i < 4; i++)
#pragma unroll
        for (int j = 0; j < 4; j++)
#pragma unroll
            for (int c = 0; c < 4; c++) acc[i][j][c] = 0.f;

    const int KT = K >> 5;

    auto load_stage = [&](int s, int kb) {
        const uint32_t dst0 = sbase + (uint32_t)(s * GSTAGE * 4);
#pragma unroll
        for (int arr = 0; arr < 4; arr++) {
            const bf16* src = (arr == 0) ? Ah_ : (arr == 1) ? Al_
                            : (arr == 2) ? Bh_ : Bl_;
            const int rbase = (arr < 2) ? m0 : n0;
#pragma unroll
            for (int it = 0; it < 2; it++) {
                const int sub = tid + it * 256;      // 0..511
                const int row = sub >> 2;            // 0..127
                const int q   = sub & 3;             // 16B chunk
                cp16(dst0 + (uint32_t)((arr * GST + row * SMW + q * 4) * 4),
                     src + (size_t)(rbase + row) * K + kb + q * 8);
            }
        }
        cp_commit();
    };

    load_stage(0, 0);
    load_stage(1, 32);

    const int arow = lane & 15;
    const int acol = (lane & 16) ? 4 : 0;
    const int brow = (lane & 7) + ((lane & 16) ? 8 : 0);
    const int bcol = (lane & 8) ? 4 : 0;

    for (int kt = 0; kt < KT; kt++) {
        cp_wait1();
        __syncthreads();
        const uint32_t st    = sbase + (uint32_t)((kt & 1) * GSTAGE * 4);
        const uint32_t offAh = st;
        const uint32_t offAl = st + GST * 4;
        const uint32_t offBh = st + 2 * GST * 4;
        const uint32_t offBl = st + 3 * GST * 4;

#pragma unroll
        for (int ks = 0; ks < 2; ks++) {
            const int kw = ks * 8;
            uint32_t bh[8], bl[8];
#pragma unroll
            for (int jp = 0; jp < 2; jp++) {
                const int rB = warp_n * 32 + jp * 16 + brow;
                const uint32_t off = (uint32_t)((rB * SMW + kw + bcol) * 4);
                ldsm4(bh[jp*4+0], bh[jp*4+1], bh[jp*4+2], bh[jp*4+3], offBh + off);
                ldsm4(bl[jp*4+0], bl[jp*4+1], bl[jp*4+2], bl[jp*4+3], offBl + off);
            }
#pragma unroll
            for (int i = 0; i < 4; i++) {
                const int rA = warp_m * 64 + i * 16 + arow;
                const uint32_t off = (uint32_t)((rA * SMW + kw + acol) * 4);
                uint32_t ah0, ah1, ah2, ah3, al0, al1, al2, al3;
                ldsm4(ah0, ah1, ah2, ah3, offAh + off);
                ldsm4(al0, al1, al2, al3, offAl + off);
#pragma unroll
                for (int j = 0; j < 4; j++) {
                    const int bi = (j >> 1) * 4 + (j & 1) * 2;
                    float* d = acc[i][j];
                    mma_bf16(d[0], d[1], d[2], d[3],
                             ah0, ah1, ah2, ah3, bh[bi], bh[bi+1]);
                    mma_bf16(d[0], d[1], d[2], d[3],
                             ah0, ah1, ah2, ah3, bl[bi], bl[bi+1]);
                    mma_bf16(d[0], d[1], d[2], d[3],
                             al0, al1, al2, al3, bh[bi], bh[bi+1]);
                }
            }
        }
        __syncthreads();
        if (kt + 2 < KT) load_stage(kt & 1, (kt + 2) * 32);
        else             cp_commit();    // keep wait-count bookkeeping exact
    }

    // epilogue
#pragma unroll
    for (int j = 0; j < 4; j++) {
        const int cn = n0 + warp_n * 32 + j * 8 + 2 * lc;
        const float2 bb = *reinterpret_cast<const float2*>(&bias[cn]);
#pragma unroll
        for (int i = 0; i < 4; i++) {
            const int r = m0 + warp_m * 64 + i * 16 + lg;
            const float v0 = acc[i][j][0] + bb.x, v1 = acc[i][j][1] + bb.y;
            const float v2 = acc[i][j][2] + bb.x, v3 = acc[i][j][3] + bb.y;
            if (SPLIT_OUT) {
                uint32_t h, l;
                split_pack(v0, v1, h, l);
                *reinterpret_cast<uint32_t*>(Ch + (size_t)r * N + cn) = h;
                *reinterpret_cast<uint32_t*>(Cl + (size_t)r * N + cn) = l;
                split_pack(v2, v3, h, l);
                *reinterpret_cast<uint32_t*>(Ch + (size_t)(r + 8) * N + cn) = h;
                *reinterpret_cast<uint32_t*>(Cl + (size_t)(r + 8) * N + cn) = l;
            } else {
                *reinterpret_cast<float2*>(&C[(size_t)r * N + cn]) =
                    make_float2(v0, v1);
                *reinterpret_cast<float2*>(&C[(size_t)(r + 8) * N + cn]) =
                    make_float2(v2, v3);
            }
        }
    }
}

__global__ __launch_bounds__(256)
void gemm_qkv_mma(const bf16* __restrict__ xh, const bf16* __restrict__ xl,
                  const float* __restrict__ bqc,
                  const float* __restrict__ bk,
                  const float* __restrict__ bv,
                  bf16* __restrict__ qkvh, bf16* __restrict__ qkvl)
{
    const int z = blockIdx.z;
    const float* b = (z == 0) ? bqc : (z == 1) ? bk : bv;
    gemm3_body<true>(xh, xl, g_wt_hi[z], g_wt_lo[z], b, nullptr,
                     qkvh + (size_t)z * MROWS * N_EMBD,
                     qkvl + (size_t)z * MROWS * N_EMBD,
                     N_EMBD, KDIM, blockIdx.x, blockIdx.y);
}

__global__ __launch_bounds__(256)
void gemm_out_mma(const bf16* __restrict__ yh, const bf16* __restrict__ yl,
                  const float* __restrict__ bo, float* __restrict__ C)
{
    gemm3_body<false>(yh, yl, g_wt_hi[3], g_wt_lo[3], bo, C, nullptr, nullptr,
                      N_EMBD, KDIM, blockIdx.x, blockIdx.y);
}

// ---------------------------------------------------------------------------
// Flash attention (byte-identical math to v5): legacy-mma bf16x3.
// ---------------------------------------------------------------------------
#define FW 36

__device__ __forceinline__ uint32_t mul_eighth(uint32_t w)
{
    bf162 v = *reinterpret_cast<bf162*>(&w);
    const bf162 s = __floats2bfloat162_rn(0.125f, 0.125f);
    v = __hmul2(v, s);
    return *reinterpret_cast<uint32_t*>(&v);
}

__global__ __launch_bounds__(256)
void flash_mma(const bf16* __restrict__ Qh, const bf16* __restrict__ Ql,
               const bf16* __restrict__ Kh, const bf16* __restrict__ Kl,
               const bf16* __restrict__ Vh, const bf16* __restrict__ Vl,
               bf16* __restrict__ Yh, bf16* __restrict__ Yl)
{
    __shared__ uint32_t sKh[64][FW];
    __shared__ uint32_t sKl[64][FW];
    __shared__ uint32_t sVh[64][FW];
    __shared__ uint32_t sVl[64][FW];

    const int tid  = threadIdx.x;
    const int lane = tid & 31;
    const int wid  = tid >> 5;
    const int g    = lane >> 2;
    const int c    = lane & 3;
    const int qb   = gridDim.x - 1 - blockIdx.x;
    const int bh   = blockIdx.y;
    const int b    = bh >> 4;
    const int h    = bh & 15;
    const size_t base = (size_t)b * SEQ * N_EMBD + (size_t)h * LATENT;

    const int r0 = qb * 128 + wid * 16 + g;
    const int r1 = r0 + 8;

    uint32_t qh[4][4], ql[4][4];
#pragma unroll
    for (int ks = 0; ks < 4; ks++) {
        const int k0a = 16 * ks + 2 * c;
        const size_t e0 = base + (size_t)r0 * N_EMBD + k0a;
        const size_t e1 = base + (size_t)r1 * N_EMBD + k0a;
        qh[ks][0] = mul_eighth(*reinterpret_cast<const uint32_t*>(Qh + e0));
        qh[ks][1] = mul_eighth(*reinterpret_cast<const uint32_t*>(Qh + e1));
        qh[ks][2] = mul_eighth(*reinterpret_cast<const uint32_t*>(Qh + e0 + 8));
        qh[ks][3] = mul_eighth(*reinterpret_cast<const uint32_t*>(Qh + e1 + 8));
        ql[ks][0] = mul_eighth(*reinterpret_cast<const uint32_t*>(Ql + e0));
        ql[ks][1] = mul_eighth(*reinterpret_cast<const uint32_t*>(Ql + e1));
        ql[ks][2] = mul_eighth(*reinterpret_cast<const uint32_t*>(Ql + e0 + 8));
        ql[ks][3] = mul_eighth(*reinterpret_cast<const uint32_t*>(Ql + e1 + 8));
    }

    float m0 = -1e30f, m1 = -1e30f, l0 = 0.f, l1 = 0.f;
    float O[8][4];
#pragma unroll
    for (int j = 0; j < 8; j++)
#pragma unroll
        for (int t = 0; t < 4; t++) O[j][t] = 0.f;

    const int jmax = 2 * qb + 1;
    for (int jb = 0; jb <= jmax; jb++) {
        __syncthreads();
#pragma unroll
        for (int it = 0; it < 4; it++) {
            const int idx = tid + it * 256;
            const int key = idx >> 4;
            const int wq  = idx & 15;
            const size_t ge = base + (size_t)(jb * 64 + key) * N_EMBD + wq * 4;
            *reinterpret_cast<uint2*>(&sKh[key][wq * 2]) =
                *reinterpret_cast<const uint2*>(Kh + ge);
            *reinterpret_cast<uint2*>(&sKl[key][wq * 2]) =
                *reinterpret_cast<const uint2*>(Kl + ge);
            const uint2 vh2 = *reinterpret_cast<const uint2*>(Vh + ge);
            const uint2 vl2 = *reinterpret_cast<const uint2*>(Vl + ge);
            const bf16* vhe = reinterpret_cast<const bf16*>(&vh2);
            const bf16* vle = reinterpret_cast<const bf16*>(&vl2);
            bf16* vhp = reinterpret_cast<bf16*>(&sVh[0][0]);
            bf16* vlp = reinterpret_cast<bf16*>(&sVl[0][0]);
#pragma unroll
            for (int e = 0; e < 4; e++) {
                vhp[(wq * 4 + e) * (2 * FW) + key] = vhe[e];
                vlp[(wq * 4 + e) * (2 * FW) + key] = vle[e];
            }
        }
        __syncthreads();

        float S[8][4];
#pragma unroll
        for (int j = 0; j < 8; j++)
#pragma unroll
            for (int t = 0; t < 4; t++) S[j][t] = 0.f;

#pragma unroll
        for (int ks = 0; ks < 4; ks++) {
#pragma unroll
            for (int j = 0; j < 8; j++) {
                const int key = 8 * j + g;
                const uint32_t bh0 = sKh[key][8 * ks + c];
                const uint32_t bh1 = sKh[key][8 * ks + 4 + c];
                const uint32_t bl0 = sKl[key][8 * ks + c];
                const uint32_t bl1 = sKl[key][8 * ks + 4 + c];
                float* d = S[j];
                mma_bf16(d[0], d[1], d[2], d[3],
                         qh[ks][0], qh[ks][1], qh[ks][2], qh[ks][3], bh0, bh1);
                mma_bf16(d[0], d[1], d[2], d[3],
                         qh[ks][0], qh[ks][1], qh[ks][2], qh[ks][3], bl0, bl1);
                mma_bf16(d[0], d[1], d[2], d[3],
                         ql[ks][0], ql[ks][1], ql[ks][2], ql[ks][3], bh0, bh1);
            }
        }

        if (jb >= 2 * qb) {
#pragma unroll
            for (int j = 0; j < 8; j++) {
                const int col = jb * 64 + 8 * j + 2 * c;
                if (col     > r0) S[j][0] = -1e30f;
                if (col + 1 > r0) S[j][1] = -1e30f;
                if (col     > r1) S[j][2] = -1e30f;
                if (col + 1 > r1) S[j][3] = -1e30f;
            }
        }

        float mx0 = -1e30f, mx1 = -1e30f;
#pragma unroll
        for (int j = 0; j < 8; j++) {
            mx0 = fmaxf(mx0, fmaxf(S[j][0], S[j][1]));
            mx1 = fmaxf(mx1, fmaxf(S[j][2], S[j][3]));
        }
        mx0 = fmaxf(mx0, __shfl_xor_sync(0xffffffffu, mx0, 1));
        mx0 = fmaxf(mx0, __shfl_xor_sync(0xffffffffu, mx0, 2));
        mx1 = fmaxf(mx1, __shfl_xor_sync(0xffffffffu, mx1, 1));
        mx1 = fmaxf(mx1, __shfl_xor_sync(0xffffffffu, mx1, 2));

        const float mn0 = fmaxf(m0, mx0);
        const float mn1 = fmaxf(m1, mx1);
        const float a0  = __expf(m0 - mn0);
        const float a1  = __expf(m1 - mn1);
        m0 = mn0; m1 = mn1;

        float rs0 = 0.f, rs1 = 0.f;
#pragma unroll
        for (int j = 0; j < 8; j++) {
            S[j][0] = __expf(S[j][0] - mn0);
            S[j][1] = __expf(S[j][1] - mn0);
            S[j][2] = __expf(S[j][2] - mn1);
            S[j][3] = __expf(S[j][3] - mn1);
            rs0 += S[j][0] + S[j][1];
            rs1 += S[j][2] + S[j][3];
        }
        rs0 += __shfl_xor_sync(0xffffffffu, rs0, 1);
        rs0 += __shfl_xor_sync(0xffffffffu, rs0, 2);
        rs1 += __shfl_xor_sync(0xffffffffu, rs1, 1);
        rs1 += __shfl_xor_sync(0xffffffffu, rs1, 2);
        l0 = l0 * a0 + rs0;
        l1 = l1 * a1 + rs1;

#pragma unroll
        for (int j = 0; j < 8; j++) {
            O[j][0] *= a0; O[j][1] *= a0;
            O[j][2] *= a1; O[j][3] *= a1;
        }

#pragma unroll
        for (int t = 0; t < 4; t++) {
            uint32_t ph0, pl0, ph1, pl1, ph2, pl2, ph3, pl3;
            split_pack(S[2 * t][0],     S[2 * t][1],     ph0, pl0);
            split_pack(S[2 * t][2],     S[2 * t][3],     ph1, pl1);
            split_pack(S[2 * t + 1][0], S[2 * t + 1][1], ph2, pl2);
            split_pack(S[2 * t + 1][2], S[2 * t + 1][3], ph3, pl3);
#pragma unroll
            for (int j = 0; j < 8; j++) {
                const int lat = 8 * j + g;
                const uint32_t bh0 = sVh[lat][8 * t + c];
                const uint32_t bh1 = sVh[lat][8 * t + 4 + c];
                const uint32_t bl0 = sVl[lat][8 * t + c];
                const uint32_t bl1 = sVl[lat][8 * t + 4 + c];
                float* d = O[j];
                mma_bf16(d[0], d[1], d[2], d[3], ph0, ph1, ph2, ph3, bh0, bh1);
                mma_bf16(d[0], d[1], d[2], d[3], ph0, ph1, ph2, ph3, bl0, bl1);
                mma_bf16(d[0], d[1], d[2], d[3], pl0, pl1, pl2, pl3, bh0, bh1);
            }
        }
    }

    const float i0 = 1.f / l0;
    const float i1 = 1.f / l1;
#pragma unroll
    for (int j = 0; j < 8; j++) {
        const int col = 8 * j + 2 * c;
        uint32_t h2, l2;
        split_pack(O[j][0] * i0, O[j][1] * i0, h2, l2);
        *reinterpret_cast<uint32_t*>(Yh + base + (size_t)r0 * N_EMBD + col) = h2;
        *reinterpret_cast<uint32_t*>(Yl + base + (size_t)r0 * N_EMBD + col) = l2;
        split_pack(O[j][2] * i1, O[j][3] * i1, h2, l2);
        *reinterpret_cast<uint32_t*>(Yh + base + (size_t)r1 * N_EMBD + col) = h2;
        *reinterpret_cast<uint32_t*>(Yl + base + (size_t)r1 * N_EMBD + col) = l2;
    }
}

// ---------------------------------------------------------------------------
// Launcher. Inputs: x,Wq,bq,Wk,bk,Wv,bv,Wo,bo,Wc
// Exactly 6 launches so ncu (-s 5 -c 1) captures gemm_out_mma.
// ---------------------------------------------------------------------------
extern "C" void kernel_launch(void* const* d_in, const int* in_sizes, int n_in,
                              void* d_out, int out_size)
{
    const float* x  = (const float*)d_in[0];
    const float* Wq = (const float*)d_in[1];
    const float* bq = (const float*)d_in[2];
    const float* Wk = (const float*)d_in[3];
    const float* bk = (const float*)d_in[4];
    const float* Wv = (const float*)d_in[5];
    const float* bv = (const float*)d_in[6];
    const float* Wo = (const float*)d_in[7];
    const float* bo = (const float*)d_in[8];
    const float* Wc = (const float*)d_in[9];
    float* out = (float*)d_out;

    float *pWqc, *pbqc;
    bf16 *pqkvh, *pqkvl, *pxh, *pxl, *pyh, *pyl, *pwh, *pwl;
    cudaGetSymbolAddress((void**)&pWqc,  g_Wqc);
    cudaGetSymbolAddress((void**)&pbqc,  g_bqc);
    cudaGetSymbolAddress((void**)&pqkvh, g_qkvh);
    cudaGetSymbolAddress((void**)&pqkvl, g_qkvl);
    cudaGetSymbolAddress((void**)&pxh,   g_xs_hi);
    cudaGetSymbolAddress((void**)&pxl,   g_xs_lo);
    cudaGetSymbolAddress((void**)&pyh,   g_ys_hi);
    cudaGetSymbolAddress((void**)&pyl,   g_ys_lo);
    cudaGetSymbolAddress((void**)&pwh,   g_wt_hi);
    cudaGetSymbolAddress((void**)&pwl,   g_wt_lo);

    const size_t MN = (size_t)MROWS * N_EMBD;

    cudaFuncSetAttribute(gemm_qkv_mma,
                         cudaFuncAttributeMaxDynamicSharedMemorySize, GEMM_SMEM);
    cudaFuncSetAttribute(gemm_out_mma,
                         cudaFuncAttributeMaxDynamicSharedMemorySize, GEMM_SMEM);

    // 1. Wqc build
    build_wqc<<<4096, 256>>>(Wq, Wc, bq, pWqc, pbqc);

    // 2. split x
    const int n2x = MROWS * N_EMBD / 2;
    split2<<<(n2x + 255) / 256, 256>>>(x, (bf162*)pxh, (bf162*)pxl, n2x);

    // 3. transpose + split all weights (one launch)
    const dim3 tg(N_EMBD / 32, N_EMBD / 32, 4);
    tsplit_all<<<tg, dim3(32, 8)>>>(pWqc, Wk, Wv, Wo, pwh, pwl);

    // 4. QKV projection
    const dim3 gq(N_EMBD / 128, MROWS / 128, 3);
    gemm_qkv_mma<<<gq, 256, GEMM_SMEM>>>(pxh, pxl, pbqc, bk, bv, pqkvh, pqkvl);

    // 5. attention
    flash_mma<<<dim3(SEQ / 128, BATCH * N_HEADS), 256>>>(
        pqkvh, pqkvl,
        pqkvh + MN, pqkvl + MN,
        pqkvh + 2 * MN, pqkvl + 2 * MN,
        pyh, pyl);

    // 6. output projection (ncu capture target)
    const dim3 gg(N_EMBD / 128, MROWS / 128);
    gemm_out_mma<<<gg, 256, GEMM_SMEM>>>(pyh, pyl, bo, out);
}

// round 11
// speedup vs baseline: 1.1480x; 1.1480x over previous
#include <cuda_runtime.h>
#include <cuda_bf16.h>
#include <cuda_fp16.h>
#include <cstdint>
#include <cstddef>

// ---------------------------------------------------------------------------
// LatentAttention v8: B=2, T=2048, n_embd=1024, heads=16, latent=64
//   - GEMMs: fp16 2-term split (A = ah+al fp16, B single fp16), 2 MMAs/step,
//     3 smem arrays, 3-stage cp.async pipeline, ldmatrix frags
//   - flash attention: bf16x3 (math unchanged); y written as fp16 hi/lo
// ---------------------------------------------------------------------------

#define N_EMBD   1024
#define N_HEADS  16
#define LATENT   64
#define BATCH    2
#define SEQ      2048
#define MROWS    (BATCH * SEQ)          // 4096
#define KDIM     1024

typedef __nv_bfloat16  bf16;
typedef __nv_bfloat162 bf162;

// ------------------------- device scratch ----------------------------------
__device__ float  g_Wqc[N_EMBD * N_EMBD];
__device__ float  g_bqc[N_EMBD];
__device__ bf16   g_qkvh[3 * MROWS * N_EMBD];   // [qc | k | v] hi (bf16, flash)
__device__ bf16   g_qkvl[3 * MROWS * N_EMBD];   // lo
__device__ __half g_xs_hi[MROWS * N_EMBD];      // x split (fp16, gemm A)
__device__ __half g_xs_lo[MROWS * N_EMBD];
__device__ __half g_ys_hi[MROWS * N_EMBD];      // y split (fp16, gemm A)
__device__ __half g_ys_lo[MROWS * N_EMBD];
__device__ __half g_wt[4][N_EMBD * N_EMBD];     // 0=Wqc 1=Wk 2=Wv 3=Wo, [N][K] fp16

// ---------------------------------------------------------------------------
__global__ void build_wqc(const float* __restrict__ Wq,
                          const float* __restrict__ Wc,
                          const float* __restrict__ bq,
                          float* __restrict__ Wqc,
                          float* __restrict__ bqc)
{
    int idx = blockIdx.x * blockDim.x + threadIdx.x;
    int c   = idx >> 10;
    int col = idx & 1023;
    int h   = col >> 6;
    int l   = col & 63;
    const float* wrow = &Wq[(size_t)c * N_EMBD + h * LATENT];
    float s = 0.f;
#pragma unroll 8
    for (int d = 0; d < LATENT; d++)
        s += wrow[d] * Wc[d * LATENT + l];
    Wqc[idx] = s;
    if (c == 0) {
        float sb = 0.f;
#pragma unroll 8
        for (int d = 0; d < LATENT; d++)
            sb += bq[h * LATENT + d] * Wc[d * LATENT + l];
        bqc[col] = sb;
    }
}

// fp32 -> fp16 hi + fp16 lo, 2 elems / thread
__global__ void split2h(const float* __restrict__ src,
                        __half2* __restrict__ hi, __half2* __restrict__ lo,
                        int n2)
{
    int i = blockIdx.x * blockDim.x + threadIdx.x;
    if (i >= n2) return;
    const float2 v = reinterpret_cast<const float2*>(src)[i];
    __half h0 = __float2half_rn(v.x);
    __half h1 = __float2half_rn(v.y);
    __half l0 = __float2half_rn(v.x - __half2float(h0));
    __half l1 = __float2half_rn(v.y - __half2float(h1));
    hi[i] = __halves2half2(h0, h1);
    lo[i] = __halves2half2(l0, l1);
}

// transpose all 4 weight matrices to [N][K] fp16 in one launch
__global__ void tsplit_all(const float* __restrict__ W0,
                           const float* __restrict__ W1,
                           const float* __restrict__ W2,
                           const float* __restrict__ W3,
                           __half* __restrict__ T)
{
    __shared__ float t[32][33];
    const int z = blockIdx.z;
    const float* W = (z == 0) ? W0 : (z == 1) ? W1 : (z == 2) ? W2 : W3;
    __half* th = T + (size_t)z * N_EMBD * N_EMBD;

    const int tx = threadIdx.x, ty = threadIdx.y;
    const int n0 = blockIdx.x * 32, k0 = blockIdx.y * 32;
#pragma unroll
    for (int i = 0; i < 4; i++)
        t[ty + 8 * i][tx] = W[(size_t)(k0 + ty + 8 * i) * N_EMBD + n0 + tx];
    __syncthreads();
#pragma unroll
    for (int i = 0; i < 4; i++) {
        const int n = n0 + ty + 8 * i;
        const int k = k0 + tx;
        th[(size_t)n * KDIM + k] = __float2half_rn(t[tx][ty + 8 * i]);
    }
}

// ---------------------------------------------------------------------------
// primitives
// ---------------------------------------------------------------------------
__device__ __forceinline__
void mma_bf16(float& d0, float& d1, float& d2, float& d3,
              uint32_t a0, uint32_t a1, uint32_t a2, uint32_t a3,
              uint32_t b0, uint32_t b1)
{
    asm volatile(
        "mma.sync.aligned.m16n8k16.row.col.f32.bf16.bf16.f32 "
        "{%0,%1,%2,%3}, {%4,%5,%6,%7}, {%8,%9}, {%0,%1,%2,%3};\n"
        : "+f"(d0), "+f"(d1), "+f"(d2), "+f"(d3)
        : "r"(a0), "r"(a1), "r"(a2), "r"(a3), "r"(b0), "r"(b1));
}

__device__ __forceinline__
void mma_f16(float& d0, float& d1, float& d2, float& d3,
             uint32_t a0, uint32_t a1, uint32_t a2, uint32_t a3,
             uint32_t b0, uint32_t b1)
{
    asm volatile(
        "mma.sync.aligned.m16n8k16.row.col.f32.f16.f16.f32 "
        "{%0,%1,%2,%3}, {%4,%5,%6,%7}, {%8,%9}, {%0,%1,%2,%3};\n"
        : "+f"(d0), "+f"(d1), "+f"(d2), "+f"(d3)
        : "r"(a0), "r"(a1), "r"(a2), "r"(a3), "r"(b0), "r"(b1));
}

// bf16 pair split (flash-internal P, and qkv storage)
__device__ __forceinline__
void split_pack(float x, float y, uint32_t& hi, uint32_t& lo)
{
    bf162 h = __floats2bfloat162_rn(x, y);
    bf162 l = __floats2bfloat162_rn(x - __bfloat162float(h.x),
                                    y - __bfloat162float(h.y));
    hi = *reinterpret_cast<uint32_t*>(&h);
    lo = *reinterpret_cast<uint32_t*>(&l);
}

// fp16 pair split (y storage)
__device__ __forceinline__
void split_pack_h(float x, float y, uint32_t& hi, uint32_t& lo)
{
    __half2 h = __floats2half2_rn(x, y);
    __half2 l = __floats2half2_rn(x - __half2float(__low2half(h)),
                                  y - __half2float(__high2half(h)));
    hi = *reinterpret_cast<uint32_t*>(&h);
    lo = *reinterpret_cast<uint32_t*>(&l);
}

__device__ __forceinline__ void cp16(uint32_t d, const void* s) {
    asm volatile("cp.async.cg.shared.global [%0], [%1], 16;" :: "r"(d), "l"(s));
}
__device__ __forceinline__ void cp_commit() {
    asm volatile("cp.async.commit_group;");
}
__device__ __forceinline__ void cp_wait2() {
    asm volatile("cp.async.wait_group 2;");
}
__device__ __forceinline__
void ldsm4(uint32_t& r0, uint32_t& r1, uint32_t& r2, uint32_t& r3, uint32_t a) {
    asm volatile("ldmatrix.sync.aligned.m8n8.x4.shared.b16 {%0,%1,%2,%3}, [%4];"
                 : "=r"(r0), "=r"(r1), "=r"(r2), "=r"(r3) : "r"(a));
}

// ---------------------------------------------------------------------------
// GEMM fp16x2: 128x128 tile, BK=32, 8 warps (2m x 4n), 3-stage cp.async,
// ldmatrix frags.  A = ah+al (fp16), B single fp16.  2 MMAs per k16 step.
// ---------------------------------------------------------------------------
#define SMW 20
#define TST (128 * SMW)            // words per array  (2560 -> 10240 B)
#define TSTG (3 * TST)             // words per stage  (3 arrays)
#define NST 3
#define GEMM_SMEM (NST * TSTG * 4) // 92160 bytes

template<bool SPLIT_OUT>
__device__ __forceinline__
void gemm2_body(const __half* __restrict__ Ah_, const __half* __restrict__ Al_,
                const __half* __restrict__ Bh_,
                const float* __restrict__ bias,
                float* __restrict__ C, bf16* __restrict__ Ch, bf16* __restrict__ Cl,
                int N, int K, int bx, int by)
{
    extern __shared__ uint32_t gsm[];
    const int tid    = threadIdx.x;
    const int lane   = tid & 31;
    const int wid    = tid >> 5;
    const int warp_m = wid >> 2;
    const int warp_n = wid & 3;
    const int m0     = by * 128;
    const int n0     = bx * 128;
    const int lg     = lane >> 2;
    const int lc     = lane & 3;
    const uint32_t sbase = (uint32_t)__cvta_generic_to_shared(gsm);

    float acc[4][4][4];
#pragma unroll
    for (int i = 0; i < 4; i++)
#pragma unroll
        for (int j = 0; j < 4; j++)
#pragma unroll
            for (int c = 0; c < 4; c++) acc[i][j][c] = 0.f;

    const int KT = K >> 5;               // 32

    auto load_stage = [&](int slot, int kb) {
        const uint32_t dst0 = sbase + (uint32_t)(slot * TSTG * 4);
#pragma unroll
        for (int arr = 0; arr < 3; arr++) {
            const __half* src = (arr == 0) ? Ah_ : (arr == 1) ? Al_ : Bh_;
            const int rbase = (arr < 2) ? m0 : n0;
#pragma unroll
            for (int it = 0; it < 2; it++) {
                const int sub = tid + it * 256;      // 0..511
                const int row = sub >> 2;            // 0..127
                const int q   = sub & 3;             // 16B chunk
                cp16(dst0 + (uint32_t)((arr * TST + row * SMW + q * 4) * 4),
                     src + (size_t)(rbase + row) * K + kb + q * 8);
            }
        }
        cp_commit();
    };

    load_stage(0, 0);
    load_stage(1, 32);
    load_stage(2, 64);

    const int arow = lane & 15;
    const int acol = (lane & 16) ? 4 : 0;
    const int brow = (lane & 7) + ((lane & 16) ? 8 : 0);
    const int bcol = (lane & 8) ? 4 : 0;

    for (int kt = 0; kt < KT; kt++) {
        cp_wait2();
        __syncthreads();
        const int slot = kt % NST;
        const uint32_t st    = sbase + (uint32_t)(slot * TSTG * 4);
        const uint32_t offAh = st;
        const uint32_t offAl = st + TST * 4;
        const uint32_t offBh = st + 2 * TST * 4;

#pragma unroll
        for (int ks = 0; ks < 2; ks++) {
            const int kw = ks * 8;
            uint32_t bh[8];
#pragma unroll
            for (int jp = 0; jp < 2; jp++) {
                const int rB = warp_n * 32 + jp * 16 + brow;
                const uint32_t off = (uint32_t)((rB * SMW + kw + bcol) * 4);
                ldsm4(bh[jp*4+0], bh[jp*4+1], bh[jp*4+2], bh[jp*4+3], offBh + off);
            }
#pragma unroll
            for (int i = 0; i < 4; i++) {
                const int rA = warp_m * 64 + i * 16 + arow;
                const uint32_t off = (uint32_t)((rA * SMW + kw + acol) * 4);
                uint32_t ah0, ah1, ah2, ah3, al0, al1, al2, al3;
                ldsm4(ah0, ah1, ah2, ah3, offAh + off);
                ldsm4(al0, al1, al2, al3, offAl + off);
#pragma unroll
                for (int j = 0; j < 4; j++) {
                    const int bi = (j >> 1) * 4 + (j & 1) * 2;
                    float* d = acc[i][j];
                    mma_f16(d[0], d[1], d[2], d[3],
                            ah0, ah1, ah2, ah3, bh[bi], bh[bi+1]);
                    mma_f16(d[0], d[1], d[2], d[3],
                            al0, al1, al2, al3, bh[bi], bh[bi+1]);
                }
            }
        }
        __syncthreads();
        if (kt + NST < KT) load_stage(slot, (kt + NST) * 32);
        else               cp_commit();   // keep wait-count bookkeeping exact
    }

    // epilogue
#pragma unroll
    for (int j = 0; j < 4; j++) {
        const int cn = n0 + warp_n * 32 + j * 8 + 2 * lc;
        const float2 bb = *reinterpret_cast<const float2*>(&bias[cn]);
#pragma unroll
        for (int i = 0; i < 4; i++) {
            const int r = m0 + warp_m * 64 + i * 16 + lg;
            const float v0 = acc[i][j][0] + bb.x, v1 = acc[i][j][1] + bb.y;
            const float v2 = acc[i][j][2] + bb.x, v3 = acc[i][j][3] + bb.y;
            if (SPLIT_OUT) {
                uint32_t h, l;
                split_pack(v0, v1, h, l);
                *reinterpret_cast<uint32_t*>(Ch + (size_t)r * N + cn) = h;
                *reinterpret_cast<uint32_t*>(Cl + (size_t)r * N + cn) = l;
                split_pack(v2, v3, h, l);
                *reinterpret_cast<uint32_t*>(Ch + (size_t)(r + 8) * N + cn) = h;
                *reinterpret_cast<uint32_t*>(Cl + (size_t)(r + 8) * N + cn) = l;
            } else {
                *reinterpret_cast<float2*>(&C[(size_t)r * N + cn]) =
                    make_float2(v0, v1);
                *reinterpret_cast<float2*>(&C[(size_t)(r + 8) * N + cn]) =
                    make_float2(v2, v3);
            }
        }
    }
}

__global__ __launch_bounds__(256)
void gemm_qkv_mma(const __half* __restrict__ xh, const __half* __restrict__ xl,
                  const float* __restrict__ bqc,
                  const float* __restrict__ bk,
                  const float* __restrict__ bv,
                  bf16* __restrict__ qkvh, bf16* __restrict__ qkvl)
{
    const int z = blockIdx.z;
    const float* b = (z == 0) ? bqc : (z == 1) ? bk : bv;
    gemm2_body<true>(xh, xl, g_wt[z], b, nullptr,
                     qkvh + (size_t)z * MROWS * N_EMBD,
                     qkvl + (size_t)z * MROWS * N_EMBD,
                     N_EMBD, KDIM, blockIdx.x, blockIdx.y);
}

__global__ __launch_bounds__(256)
void gemm_out_mma(const __half* __restrict__ yh, const __half* __restrict__ yl,
                  const float* __restrict__ bo, float* __restrict__ C)
{
    gemm2_body<false>(yh, yl, g_wt[3], bo, C, nullptr, nullptr,
                      N_EMBD, KDIM, blockIdx.x, blockIdx.y);
}

// ---------------------------------------------------------------------------
// Flash attention (bf16x3 math unchanged); y written as fp16 hi/lo.
// ---------------------------------------------------------------------------
#define FW 36

__device__ __forceinline__ uint32_t mul_eighth(uint32_t w)
{
    bf162 v = *reinterpret_cast<bf162*>(&w);
    const bf162 s = __floats2bfloat162_rn(0.125f, 0.125f);
    v = __hmul2(v, s);
    return *reinterpret_cast<uint32_t*>(&v);
}

__global__ __launch_bounds__(256)
void flash_mma(const bf16* __restrict__ Qh, const bf16* __restrict__ Ql,
               const bf16* __restrict__ Kh, const bf16* __restrict__ Kl,
               const bf16* __restrict__ Vh, const bf16* __restrict__ Vl,
               __half* __restrict__ Yh, __half* __restrict__ Yl)
{
    __shared__ uint32_t sKh[64][FW];
    __shared__ uint32_t sKl[64][FW];
    __shared__ uint32_t sVh[64][FW];
    __shared__ uint32_t sVl[64][FW];

    const int tid  = threadIdx.x;
    const int lane = tid & 31;
    const int wid  = tid >> 5;
    const int g    = lane >> 2;
    const int c    = lane & 3;
    const int qb   = gridDim.x - 1 - blockIdx.x;
    const int bh   = blockIdx.y;
    const int b    = bh >> 4;
    const int h    = bh & 15;
    const size_t base = (size_t)b * SEQ * N_EMBD + (size_t)h * LATENT;

    const int r0 = qb * 128 + wid * 16 + g;
    const int r1 = r0 + 8;

    uint32_t qh[4][4], ql[4][4];
#pragma unroll
    for (int ks = 0; ks < 4; ks++) {
        const int k0a = 16 * ks + 2 * c;
        const size_t e0 = base + (size_t)r0 * N_EMBD + k0a;
        const size_t e1 = base + (size_t)r1 * N_EMBD + k0a;
        qh[ks][0] = mul_eighth(*reinterpret_cast<const uint32_t*>(Qh + e0));
        qh[ks][1] = mul_eighth(*reinterpret_cast<const uint32_t*>(Qh + e1));
        qh[ks][2] = mul_eighth(*reinterpret_cast<const uint32_t*>(Qh + e0 + 8));
        qh[ks][3] = mul_eighth(*reinterpret_cast<const uint32_t*>(Qh + e1 + 8));
        ql[ks][0] = mul_eighth(*reinterpret_cast<const uint32_t*>(Ql + e0));
        ql[ks][1] = mul_eighth(*reinterpret_cast<const uint32_t*>(Ql + e1));
        ql[ks][2] = mul_eighth(*reinterpret_cast<const uint32_t*>(Ql + e0 + 8));
        ql[ks][3] = mul_eighth(*reinterpret_cast<const uint32_t*>(Ql + e1 + 8));
    }

    float m0 = -1e30f, m1 = -1e30f, l0 = 0.f, l1 = 0.f;
    float O[8][4];
#pragma unroll
    for (int j = 0; j < 8; j++)
#pragma unroll
        for (int t = 0; t < 4; t++) O[j][t] = 0.f;

    const int jmax = 2 * qb + 1;
    for (int jb = 0; jb <= jmax; jb++) {
        __syncthreads();
#pragma unroll
        for (int it = 0; it < 4; it++) {
            const int idx = tid + it * 256;
            const int key = idx >> 4;
            const int wq  = idx & 15;
            const size_t ge = base + (size_t)(jb * 64 + key) * N_EMBD + wq * 4;
            *reinterpret_cast<uint2*>(&sKh[key][wq * 2]) =
                *reinterpret_cast<const uint2*>(Kh + ge);
            *reinterpret_cast<uint2*>(&sKl[key][wq * 2]) =
                *reinterpret_cast<const uint2*>(Kl + ge);
            const uint2 vh2 = *reinterpret_cast<const uint2*>(Vh + ge);
            const uint2 vl2 = *reinterpret_cast<const uint2*>(Vl + ge);
            const bf16* vhe = reinterpret_cast<const bf16*>(&vh2);
            const bf16* vle = reinterpret_cast<const bf16*>(&vl2);
            bf16* vhp = reinterpret_cast<bf16*>(&sVh[0][0]);
            bf16* vlp = reinterpret_cast<bf16*>(&sVl[0][0]);
#pragma unroll
            for (int e = 0; e < 4; e++) {
                vhp[(wq * 4 + e) * (2 * FW) + key] = vhe[e];
                vlp[(wq * 4 + e) * (2 * FW) + key] = vle[e];
            }
        }
        __syncthreads();

        float S[8][4];
#pragma unroll
        for (int j = 0; j < 8; j++)
#pragma unroll
            for (int t = 0; t < 4; t++) S[j][t] = 0.f;

#pragma unroll
        for (int ks = 0; ks < 4; ks++) {
#pragma unroll
            for (int j = 0; j < 8; j++) {
                const int key = 8 * j + g;
                const uint32_t bh0 = sKh[key][8 * ks + c];
                const uint32_t bh1 = sKh[key][8 * ks + 4 + c];
                const uint32_t bl0 = sKl[key][8 * ks + c];
                const uint32_t bl1 = sKl[key][8 * ks + 4 + c];
                float* d = S[j];
                mma_bf16(d[0], d[1], d[2], d[3],
                         qh[ks][0], qh[ks][1], qh[ks][2], qh[ks][3], bh0, bh1);
                mma_bf16(d[0], d[1], d[2], d[3],
                         qh[ks][0], qh[ks][1], qh[ks][2], qh[ks][3], bl0, bl1);
                mma_bf16(d[0], d[1], d[2], d[3],
                         ql[ks][0], ql[ks][1], ql[ks][2], ql[ks][3], bh0, bh1);
            }
        }

        if (jb >= 2 * qb) {
#pragma unroll
            for (int j = 0; j < 8; j++) {
                const int col = jb * 64 + 8 * j + 2 * c;
                if (col     > r0) S[j][0] = -1e30f;
                if (col + 1 > r0) S[j][1] = -1e30f;
                if (col     > r1) S[j][2] = -1e30f;
                if (col + 1 > r1) S[j][3] = -1e30f;
            }
        }

        float mx0 = -1e30f, mx1 = -1e30f;
#pragma unroll
        for (int j = 0; j < 8; j++) {
            mx0 = fmaxf(mx0, fmaxf(S[j][0], S[j][1]));
            mx1 = fmaxf(mx1, fmaxf(S[j][2], S[j][3]));
        }
        mx0 = fmaxf(mx0, __shfl_xor_sync(0xffffffffu, mx0, 1));
        mx0 = fmaxf(mx0, __shfl_xor_sync(0xffffffffu, mx0, 2));
        mx1 = fmaxf(mx1, __shfl_xor_sync(0xffffffffu, mx1, 1));
        mx1 = fmaxf(mx1, __shfl_xor_sync(0xffffffffu, mx1, 2));

        const float mn0 = fmaxf(m0, mx0);
        const float mn1 = fmaxf(m1, mx1);
        const float a0  = __expf(m0 - mn0);
        const float a1  = __expf(m1 - mn1);
        m0 = mn0; m1 = mn1;

        float rs0 = 0.f, rs1 = 0.f;
#pragma unroll
        for (int j = 0; j < 8; j++) {
            S[j][0] = __expf(S[j][0] - mn0);
            S[j][1] = __expf(S[j][1] - mn0);
            S[j][2] = __expf(S[j][2] - mn1);
            S[j][3] = __expf(S[j][3] - mn1);
            rs0 += S[j][0] + S[j][1];
            rs1 += S[j][2] + S[j][3];
        }
        rs0 += __shfl_xor_sync(0xffffffffu, rs0, 1);
        rs0 += __shfl_xor_sync(0xffffffffu, rs0, 2);
        rs1 += __shfl_xor_sync(0xffffffffu, rs1, 1);
        rs1 += __shfl_xor_sync(0xffffffffu, rs1, 2);
        l0 = l0 * a0 + rs0;
        l1 = l1 * a1 + rs1;

#pragma unroll
        for (int j = 0; j < 8; j++) {
            O[j][0] *= a0; O[j][1] *= a0;
            O[j][2] *= a1; O[j][3] *= a1;
        }

#pragma unroll
        for (int t = 0; t < 4; t++) {
            uint32_t ph0, pl0, ph1, pl1, ph2, pl2, ph3, pl3;
            split_pack(S[2 * t][0],     S[2 * t][1],     ph0, pl0);
            split_pack(S[2 * t][2],     S[2 * t][3],     ph1, pl1);
            split_pack(S[2 * t + 1][0], S[2 * t + 1][1], ph2, pl2);
            split_pack(S[2 * t + 1][2], S[2 * t + 1][3], ph3, pl3);
#pragma unroll
            for (int j = 0; j < 8; j++) {
                const int lat = 8 * j + g;
                const uint32_t bh0 = sVh[lat][8 * t + c];
                const uint32_t bh1 = sVh[lat][8 * t + 4 + c];
                const uint32_t bl0 = sVl[lat][8 * t + c];
                const uint32_t bl1 = sVl[lat][8 * t + 4 + c];
                float* d = O[j];
                mma_bf16(d[0], d[1], d[2], d[3], ph0, ph1, ph2, ph3, bh0, bh1);
                mma_bf16(d[0], d[1], d[2], d[3], ph0, ph1, ph2, ph3, bl0, bl1);
                mma_bf16(d[0], d[1], d[2], d[3], pl0, pl1, pl2, pl3, bh0, bh1);
            }
        }
    }

    const float i0 = 1.f / l0;
    const float i1 = 1.f / l1;
#pragma unroll
    for (int j = 0; j < 8; j++) {
        const int col = 8 * j + 2 * c;
        uint32_t h2, l2;
        split_pack_h(O[j][0] * i0, O[j][1] * i0, h2, l2);
        *reinterpret_cast<uint32_t*>(Yh + base + (size_t)r0 * N_EMBD + col) = h2;
        *reinterpret_cast<uint32_t*>(Yl + base + (size_t)r0 * N_EMBD + col) = l2;
        split_pack_h(O[j][2] * i1, O[j][3] * i1, h2, l2);
        *reinterpret_cast<uint32_t*>(Yh + base + (size_t)r1 * N_EMBD + col) = h2;
        *reinterpret_cast<uint32_t*>(Yl + base + (size_t)r1 * N_EMBD + col) = l2;
    }
}

// ---------------------------------------------------------------------------
// Launcher. Inputs: x,Wq,bq,Wk,bk,Wv,bv,Wo,bo,Wc   (6 launches total)
// ---------------------------------------------------------------------------
extern "C" void kernel_launch(void* const* d_in, const int* in_sizes, int n_in,
                              void* d_out, int out_size)
{
    const float* x  = (const float*)d_in[0];
    const float* Wq = (const float*)d_in[1];
    const float* bq = (const float*)d_in[2];
    const float* Wk = (const float*)d_in[3];
    const float* bk = (const float*)d_in[4];
    const float* Wv = (const float*)d_in[5];
    const float* bv = (const float*)d_in[6];
    const float* Wo = (const float*)d_in[7];
    const float* bo = (const float*)d_in[8];
    const float* Wc = (const float*)d_in[9];
    float* out = (float*)d_out;

    float *pWqc, *pbqc;
    bf16 *pqkvh, *pqkvl;
    __half *pxh, *pxl, *pyh, *pyl, *pwt;
    cudaGetSymbolAddress((void**)&pWqc,  g_Wqc);
    cudaGetSymbolAddress((void**)&pbqc,  g_bqc);
    cudaGetSymbolAddress((void**)&pqkvh, g_qkvh);
    cudaGetSymbolAddress((void**)&pqkvl, g_qkvl);
    cudaGetSymbolAddress((void**)&pxh,   g_xs_hi);
    cudaGetSymbolAddress((void**)&pxl,   g_xs_lo);
    cudaGetSymbolAddress((void**)&pyh,   g_ys_hi);
    cudaGetSymbolAddress((void**)&pyl,   g_ys_lo);
    cudaGetSymbolAddress((void**)&pwt,   g_wt);

    const size_t MN = (size_t)MROWS * N_EMBD;

    cudaFuncSetAttribute(gemm_qkv_mma,
                         cudaFuncAttributeMaxDynamicSharedMemorySize, GEMM_SMEM);
    cudaFuncSetAttribute(gemm_out_mma,
                         cudaFuncAttributeMaxDynamicSharedMemorySize, GEMM_SMEM);

    // 1. Wqc build
    build_wqc<<<4096, 256>>>(Wq, Wc, bq, pWqc, pbqc);

    // 2. split x (fp16)
    const int n2x = MROWS * N_EMBD / 2;
    split2h<<<(n2x + 255) / 256, 256>>>(x, (__half2*)pxh, (__half2*)pxl, n2x);

    // 3. transpose all weights to [N][K] fp16 (one launch)
    const dim3 tg(N_EMBD / 32, N_EMBD / 32, 4);
    tsplit_all<<<tg, dim3(32, 8)>>>(pWqc, Wk, Wv, Wo, pwt);

    // 4. QKV projection (fp16x2 -> bf16-split outputs)
    const dim3 gq(N_EMBD / 128, MROWS / 128, 3);
    gemm_qkv_mma<<<gq, 256, GEMM_SMEM>>>(pxh, pxl, pbqc, bk, bv, pqkvh, pqkvl);

    // 5. attention (bf16x3; writes fp16-split y)
    flash_mma<<<dim3(SEQ / 128, BATCH * N_HEADS), 256>>>(
        pqkvh, pqkvl,
        pqkvh + MN, pqkvl + MN,
        pqkvh + 2 * MN, pqkvl + 2 * MN,
        pyh, pyl);

    // 6. output projection (fp16x2, ncu capture target)
    const dim3 gg(N_EMBD / 128, MROWS / 128);
    gemm_out_mma<<<gg, 256, GEMM_SMEM>>>(pyh, pyl, bo, out);
}

// round 12
// speedup vs baseline: 1.4607x; 1.2723x over previous
#include <cuda_runtime.h>
#include <cuda_bf16.h>
#include <cuda_fp16.h>
#include <cstdint>
#include <cstddef>

// ---------------------------------------------------------------------------
// LatentAttention v9: B=2, T=2048, n_embd=1024, heads=16, latent=64
//   - GEMMs: fp16x2 (A split, B single), single-barrier 3-stage pipeline
//   - flash: fp16 throughout — QK^T 2 MMAs (Q split, K single),
//     PV 1 MMA (P,V single fp16), fp32 softmax
// ---------------------------------------------------------------------------

#define N_EMBD   1024
#define N_HEADS  16
#define LATENT   64
#define BATCH    2
#define SEQ      2048
#define MROWS    (BATCH * SEQ)          // 4096
#define KDIM     1024

// ------------------------- device scratch ----------------------------------
__device__ float  g_Wqc[N_EMBD * N_EMBD];
__device__ float  g_bqc[N_EMBD];
__device__ __half g_qkvh[3 * MROWS * N_EMBD];   // [qc | k | v] hi (fp16)
__device__ __half g_qkvl[3 * MROWS * N_EMBD];   // lo (only qc slice used)
__device__ __half g_xs_hi[MROWS * N_EMBD];
__device__ __half g_xs_lo[MROWS * N_EMBD];
__device__ __half g_ys_hi[MROWS * N_EMBD];
__device__ __half g_ys_lo[MROWS * N_EMBD];
__device__ __half g_wt[4][N_EMBD * N_EMBD];     // 0=Wqc 1=Wk 2=Wv 3=Wo, [N][K]

// ---------------------------------------------------------------------------
__global__ void build_wqc(const float* __restrict__ Wq,
                          const float* __restrict__ Wc,
                          const float* __restrict__ bq,
                          float* __restrict__ Wqc,
                          float* __restrict__ bqc)
{
    int idx = blockIdx.x * blockDim.x + threadIdx.x;
    int c   = idx >> 10;
    int col = idx & 1023;
    int h   = col >> 6;
    int l   = col & 63;
    const float* wrow = &Wq[(size_t)c * N_EMBD + h * LATENT];
    float s = 0.f;
#pragma unroll 8
    for (int d = 0; d < LATENT; d++)
        s += wrow[d] * Wc[d * LATENT + l];
    Wqc[idx] = s;
    if (c == 0) {
        float sb = 0.f;
#pragma unroll 8
        for (int d = 0; d < LATENT; d++)
            sb += bq[h * LATENT + d] * Wc[d * LATENT + l];
        bqc[col] = sb;
    }
}

__global__ void split2h(const float* __restrict__ src,
                        __half2* __restrict__ hi, __half2* __restrict__ lo,
                        int n2)
{
    int i = blockIdx.x * blockDim.x + threadIdx.x;
    if (i >= n2) return;
    const float2 v = reinterpret_cast<const float2*>(src)[i];
    __half h0 = __float2half_rn(v.x);
    __half h1 = __float2half_rn(v.y);
    __half l0 = __float2half_rn(v.x - __half2float(h0));
    __half l1 = __float2half_rn(v.y - __half2float(h1));
    hi[i] = __halves2half2(h0, h1);
    lo[i] = __halves2half2(l0, l1);
}

__global__ void tsplit_all(const float* __restrict__ W0,
                           const float* __restrict__ W1,
                           const float* __restrict__ W2,
                           const float* __restrict__ W3,
                           __half* __restrict__ T)
{
    __shared__ float t[32][33];
    const int z = blockIdx.z;
    const float* W = (z == 0) ? W0 : (z == 1) ? W1 : (z == 2) ? W2 : W3;
    __half* th = T + (size_t)z * N_EMBD * N_EMBD;

    const int tx = threadIdx.x, ty = threadIdx.y;
    const int n0 = blockIdx.x * 32, k0 = blockIdx.y * 32;
#pragma unroll
    for (int i = 0; i < 4; i++)
        t[ty + 8 * i][tx] = W[(size_t)(k0 + ty + 8 * i) * N_EMBD + n0 + tx];
    __syncthreads();
#pragma unroll
    for (int i = 0; i < 4; i++) {
        const int n = n0 + ty + 8 * i;
        const int k = k0 + tx;
        th[(size_t)n * KDIM + k] = __float2half_rn(t[tx][ty + 8 * i]);
    }
}

// ---------------------------------------------------------------------------
// primitives
// ---------------------------------------------------------------------------
__device__ __forceinline__
void mma_f16(float& d0, float& d1, float& d2, float& d3,
             uint32_t a0, uint32_t a1, uint32_t a2, uint32_t a3,
             uint32_t b0, uint32_t b1)
{
    asm volatile(
        "mma.sync.aligned.m16n8k16.row.col.f32.f16.f16.f32 "
        "{%0,%1,%2,%3}, {%4,%5,%6,%7}, {%8,%9}, {%0,%1,%2,%3};\n"
        : "+f"(d0), "+f"(d1), "+f"(d2), "+f"(d3)
        : "r"(a0), "r"(a1), "r"(a2), "r"(a3), "r"(b0), "r"(b1));
}

__device__ __forceinline__
void split_pack_h(float x, float y, uint32_t& hi, uint32_t& lo)
{
    __half2 h = __floats2half2_rn(x, y);
    __half2 l = __floats2half2_rn(x - __half2float(__low2half(h)),
                                  y - __half2float(__high2half(h)));
    hi = *reinterpret_cast<uint32_t*>(&h);
    lo = *reinterpret_cast<uint32_t*>(&l);
}

__device__ __forceinline__ uint32_t pack_h(float x, float y)
{
    __half2 h = __floats2half2_rn(x, y);
    return *reinterpret_cast<uint32_t*>(&h);
}

__device__ __forceinline__ uint32_t mul8h(uint32_t w)
{
    __half2 v = *reinterpret_cast<__half2*>(&w);
    v = __hmul2(v, __floats2half2_rn(0.125f, 0.125f));   // 2^-3 exact
    return *reinterpret_cast<uint32_t*>(&v);
}

__device__ __forceinline__ void cp16(uint32_t d, const void* s) {
    asm volatile("cp.async.cg.shared.global [%0], [%1], 16;" :: "r"(d), "l"(s));
}
__device__ __forceinline__ void cp_commit() {
    asm volatile("cp.async.commit_group;");
}
__device__ __forceinline__ void cp_wait1() {
    asm volatile("cp.async.wait_group 1;");
}
__device__ __forceinline__
void ldsm4(uint32_t& r0, uint32_t& r1, uint32_t& r2, uint32_t& r3, uint32_t a) {
    asm volatile("ldmatrix.sync.aligned.m8n8.x4.shared.b16 {%0,%1,%2,%3}, [%4];"
                 : "=r"(r0), "=r"(r1), "=r"(r2), "=r"(r3) : "r"(a));
}

// ---------------------------------------------------------------------------
// GEMM fp16x2: 128x128 tile, BK=32, 8 warps (2m x 4n), 3-stage cp.async,
// ONE barrier per k-tile (loads for stage kt+2 target the slot freed at kt-1).
// ---------------------------------------------------------------------------
#define SMW 20
#define TST (128 * SMW)            // words per array
#define TSTG (3 * TST)             // words per stage (Ah, Al, B)
#define NST 3
#define GEMM_SMEM (NST * TSTG * 4) // 92160 bytes

template<bool SPLIT_OUT>
__device__ __forceinline__
void gemm2_body(const __half* __restrict__ Ah_, const __half* __restrict__ Al_,
                const __half* __restrict__ Bh_,
                const float* __restrict__ bias,
                float* __restrict__ C,
                __half* __restrict__ Ch, __half* __restrict__ Cl, bool write_lo,
                int N, int K, int bx, int by)
{
    extern __shared__ uint32_t gsm[];
    const int tid    = threadIdx.x;
    const int lane   = tid & 31;
    const int wid    = tid >> 5;
    const int warp_m = wid >> 2;
    const int warp_n = wid & 3;
    const int m0     = by * 128;
    const int n0     = bx * 128;
    const int lg     = lane >> 2;
    const int lc     = lane & 3;
    const uint32_t sbase = (uint32_t)__cvta_generic_to_shared(gsm);

    float acc[4][4][4];
#pragma unroll
    for (int i = 0; i < 4; i++)
#pragma unroll
        for (int j = 0; j < 4; j++)
#pragma unroll
            for (int c = 0; c < 4; c++) acc[i][j][c] = 0.f;

    const int KT = K >> 5;               // 32

    auto load_stage = [&](int slot, int kb) {
        const uint32_t dst0 = sbase + (uint32_t)(slot * TSTG * 4);
#pragma unroll
        for (int arr = 0; arr < 3; arr++) {
            const __half* src = (arr == 0) ? Ah_ : (arr == 1) ? Al_ : Bh_;
            const int rbase = (arr < 2) ? m0 : n0;
#pragma unroll
            for (int it = 0; it < 2; it++) {
                const int sub = tid + it * 256;      // 0..511
                const int row = sub >> 2;            // 0..127
                const int q   = sub & 3;             // 16B chunk
                cp16(dst0 + (uint32_t)((arr * TST + row * SMW + q * 4) * 4),
                     src + (size_t)(rbase + row) * K + kb + q * 8);
            }
        }
        cp_commit();
    };

    // prologue: stages 0,1
    load_stage(0, 0);
    load_stage(1, 32);

    const int arow = lane & 15;
    const int acol = (lane & 16) ? 4 : 0;
    const int brow = (lane & 7) + ((lane & 16) ? 8 : 0);
    const int bcol = (lane & 8) ? 4 : 0;

    for (int kt = 0; kt < KT; kt++) {
        cp_wait1();                       // stage kt resident
        __syncthreads();                  // all warps done with slot (kt-1)%3
        if (kt + 2 < KT) load_stage((kt + 2) % NST, (kt + 2) * 32);
        else             cp_commit();     // keep group accounting exact

        const int slot = kt % NST;
        const uint32_t st    = sbase + (uint32_t)(slot * TSTG * 4);
        const uint32_t offAh = st;
        const uint32_t offAl = st + TST * 4;
        const uint32_t offB  = st + 2 * TST * 4;

#pragma unroll
        for (int ks = 0; ks < 2; ks++) {
            const int kw = ks * 8;
            uint32_t bh[8];
#pragma unroll
            for (int jp = 0; jp < 2; jp++) {
                const int rB = warp_n * 32 + jp * 16 + brow;
                const uint32_t off = (uint32_t)((rB * SMW + kw + bcol) * 4);
                ldsm4(bh[jp*4+0], bh[jp*4+1], bh[jp*4+2], bh[jp*4+3], offB + off);
            }
#pragma unroll
            for (int i = 0; i < 4; i++) {
                const int rA = warp_m * 64 + i * 16 + arow;
                const uint32_t off = (uint32_t)((rA * SMW + kw + acol) * 4);
                uint32_t ah0, ah1, ah2, ah3, al0, al1, al2, al3;
                ldsm4(ah0, ah1, ah2, ah3, offAh + off);
                ldsm4(al0, al1, al2, al3, offAl + off);
#pragma unroll
                for (int j = 0; j < 4; j++) {
                    const int bi = (j >> 1) * 4 + (j & 1) * 2;
                    float* d = acc[i][j];
                    mma_f16(d[0], d[1], d[2], d[3],
                            ah0, ah1, ah2, ah3, bh[bi], bh[bi+1]);
                    mma_f16(d[0], d[1], d[2], d[3],
                            al0, al1, al2, al3, bh[bi], bh[bi+1]);
                }
            }
        }
    }

    // epilogue
#pragma unroll
    for (int j = 0; j < 4; j++) {
        const int cn = n0 + warp_n * 32 + j * 8 + 2 * lc;
        const float2 bb = *reinterpret_cast<const float2*>(&bias[cn]);
#pragma unroll
        for (int i = 0; i < 4; i++) {
            const int r = m0 + warp_m * 64 + i * 16 + lg;
            const float v0 = acc[i][j][0] + bb.x, v1 = acc[i][j][1] + bb.y;
            const float v2 = acc[i][j][2] + bb.x, v3 = acc[i][j][3] + bb.y;
            if (SPLIT_OUT) {
                uint32_t h, l;
                split_pack_h(v0, v1, h, l);
                *reinterpret_cast<uint32_t*>(Ch + (size_t)r * N + cn) = h;
                if (write_lo)
                    *reinterpret_cast<uint32_t*>(Cl + (size_t)r * N + cn) = l;
                split_pack_h(v2, v3, h, l);
                *reinterpret_cast<uint32_t*>(Ch + (size_t)(r + 8) * N + cn) = h;
                if (write_lo)
                    *reinterpret_cast<uint32_t*>(Cl + (size_t)(r + 8) * N + cn) = l;
            } else {
                *reinterpret_cast<float2*>(&C[(size_t)r * N + cn]) =
                    make_float2(v0, v1);
                *reinterpret_cast<float2*>(&C[(size_t)(r + 8) * N + cn]) =
                    make_float2(v2, v3);
            }
        }
    }
}

__global__ __launch_bounds__(256)
void gemm_qkv_mma(const __half* __restrict__ xh, const __half* __restrict__ xl,
                  const float* __restrict__ bqc,
                  const float* __restrict__ bk,
                  const float* __restrict__ bv,
                  __half* __restrict__ qkvh, __half* __restrict__ qkvl)
{
    const int z = blockIdx.z;
    const float* b = (z == 0) ? bqc : (z == 1) ? bk : bv;
    gemm2_body<true>(xh, xl, g_wt[z], b, nullptr,
                     qkvh + (size_t)z * MROWS * N_EMBD,
                     qkvl + (size_t)z * MROWS * N_EMBD, (z == 0),
                     N_EMBD, KDIM, blockIdx.x, blockIdx.y);
}

__global__ __launch_bounds__(256)
void gemm_out_mma(const __half* __restrict__ yh, const __half* __restrict__ yl,
                  const float* __restrict__ bo, float* __restrict__ C)
{
    gemm2_body<false>(yh, yl, g_wt[3], bo, C, nullptr, nullptr, false,
                      N_EMBD, KDIM, blockIdx.x, blockIdx.y);
}

// ---------------------------------------------------------------------------
// Flash attention v9 — all fp16 MMA: QK^T = qh·k + ql·k (2), PV = p·v (1).
// 256 threads = 8 warps; 128 q-rows (16/warp), 64-key tiles; fp32 softmax.
// ---------------------------------------------------------------------------
#define FW 36

__global__ __launch_bounds__(256)
void flash_mma(const __half* __restrict__ Qh, const __half* __restrict__ Ql,
               const __half* __restrict__ Kg, const __half* __restrict__ Vg,
               __half* __restrict__ Yh, __half* __restrict__ Yl)
{
    __shared__ uint32_t sK[64][FW];   // [key][lat-pair]  fp16
    __shared__ uint32_t sV[64][FW];   // [lat][key-pair]  fp16 (transposed)

    const int tid  = threadIdx.x;
    const int lane = tid & 31;
    const int wid  = tid >> 5;
    const int g    = lane >> 2;
    const int c    = lane & 3;
    const int qb   = gridDim.x - 1 - blockIdx.x;   // long blocks first
    const int bh   = blockIdx.y;
    const int b    = bh >> 4;
    const int h    = bh & 15;
    const size_t base = (size_t)b * SEQ * N_EMBD + (size_t)h * LATENT;

    const int r0 = qb * 128 + wid * 16 + g;
    const int r1 = r0 + 8;

    // Q fragments (fp16 hi/lo), 1/8 scale folded in (exact)
    uint32_t qh[4][4], ql[4][4];
#pragma unroll
    for (int ks = 0; ks < 4; ks++) {
        const int k0a = 16 * ks + 2 * c;
        const size_t e0 = base + (size_t)r0 * N_EMBD + k0a;
        const size_t e1 = base + (size_t)r1 * N_EMBD + k0a;
        qh[ks][0] = mul8h(*reinterpret_cast<const uint32_t*>(Qh + e0));
        qh[ks][1] = mul8h(*reinterpret_cast<const uint32_t*>(Qh + e1));
        qh[ks][2] = mul8h(*reinterpret_cast<const uint32_t*>(Qh + e0 + 8));
        qh[ks][3] = mul8h(*reinterpret_cast<const uint32_t*>(Qh + e1 + 8));
        ql[ks][0] = mul8h(*reinterpret_cast<const uint32_t*>(Ql + e0));
        ql[ks][1] = mul8h(*reinterpret_cast<const uint32_t*>(Ql + e1));
        ql[ks][2] = mul8h(*reinterpret_cast<const uint32_t*>(Ql + e0 + 8));
        ql[ks][3] = mul8h(*reinterpret_cast<const uint32_t*>(Ql + e1 + 8));
    }

    float m0 = -1e30f, m1 = -1e30f, l0 = 0.f, l1 = 0.f;
    float O[8][4];
#pragma unroll
    for (int j = 0; j < 8; j++)
#pragma unroll
        for (int t = 0; t < 4; t++) O[j][t] = 0.f;

    const int jmax = 2 * qb + 1;
    for (int jb = 0; jb <= jmax; jb++) {
        __syncthreads();
        // load K (natural) + V (transposed) fp16 tiles
#pragma unroll
        for (int it = 0; it < 4; it++) {
            const int idx = tid + it * 256;        // 0..1023
            const int key = idx >> 4;              // 0..63
            const int wq  = idx & 15;              // 4-lat group
            const size_t ge = base + (size_t)(jb * 64 + key) * N_EMBD + wq * 4;
            *reinterpret_cast<uint2*>(&sK[key][wq * 2]) =
                *reinterpret_cast<const uint2*>(Kg + ge);
            const uint2 vv = *reinterpret_cast<const uint2*>(Vg + ge);
            const __half* ve = reinterpret_cast<const __half*>(&vv);
            __half* vp = reinterpret_cast<__half*>(&sV[0][0]);
#pragma unroll
            for (int e = 0; e < 4; e++)
                vp[(wq * 4 + e) * (2 * FW) + key] = ve[e];
        }
        __syncthreads();

        // S = Q . K^T (2 fp16 MMAs per step)
        float S[8][4];
#pragma unroll
        for (int j = 0; j < 8; j++)
#pragma unroll
            for (int t = 0; t < 4; t++) S[j][t] = 0.f;

#pragma unroll
        for (int ks = 0; ks < 4; ks++) {
#pragma unroll
            for (int j = 0; j < 8; j++) {
                const int key = 8 * j + g;
                const uint32_t b0 = sK[key][8 * ks + c];
                const uint32_t b1 = sK[key][8 * ks + 4 + c];
                float* d = S[j];
                mma_f16(d[0], d[1], d[2], d[3],
                        qh[ks][0], qh[ks][1], qh[ks][2], qh[ks][3], b0, b1);
                mma_f16(d[0], d[1], d[2], d[3],
                        ql[ks][0], ql[ks][1], ql[ks][2], ql[ks][3], b0, b1);
            }
        }

        // causal mask
        if (jb >= 2 * qb) {
#pragma unroll
            for (int j = 0; j < 8; j++) {
                const int col = jb * 64 + 8 * j + 2 * c;
                if (col     > r0) S[j][0] = -1e30f;
                if (col + 1 > r0) S[j][1] = -1e30f;
                if (col     > r1) S[j][2] = -1e30f;
                if (col + 1 > r1) S[j][3] = -1e30f;
            }
        }

        // online softmax (fp32)
        float mx0 = -1e30f, mx1 = -1e30f;
#pragma unroll
        for (int j = 0; j < 8; j++) {
            mx0 = fmaxf(mx0, fmaxf(S[j][0], S[j][1]));
            mx1 = fmaxf(mx1, fmaxf(S[j][2], S[j][3]));
        }
        mx0 = fmaxf(mx0, __shfl_xor_sync(0xffffffffu, mx0, 1));
        mx0 = fmaxf(mx0, __shfl_xor_sync(0xffffffffu, mx0, 2));
        mx1 = fmaxf(mx1, __shfl_xor_sync(0xffffffffu, mx1, 1));
        mx1 = fmaxf(mx1, __shfl_xor_sync(0xffffffffu, mx1, 2));

        const float mn0 = fmaxf(m0, mx0);
        const float mn1 = fmaxf(m1, mx1);
        const float a0  = __expf(m0 - mn0);
        const float a1  = __expf(m1 - mn1);
        m0 = mn0; m1 = mn1;

        float rs0 = 0.f, rs1 = 0.f;
#pragma unroll
        for (int j = 0; j < 8; j++) {
            S[j][0] = __expf(S[j][0] - mn0);
            S[j][1] = __expf(S[j][1] - mn0);
            S[j][2] = __expf(S[j][2] - mn1);
            S[j][3] = __expf(S[j][3] - mn1);
            rs0 += S[j][0] + S[j][1];
            rs1 += S[j][2] + S[j][3];
        }
        rs0 += __shfl_xor_sync(0xffffffffu, rs0, 1);
        rs0 += __shfl_xor_sync(0xffffffffu, rs0, 2);
        rs1 += __shfl_xor_sync(0xffffffffu, rs1, 1);
        rs1 += __shfl_xor_sync(0xffffffffu, rs1, 2);
        l0 = l0 * a0 + rs0;
        l1 = l1 * a1 + rs1;

#pragma unroll
        for (int j = 0; j < 8; j++) {
            O[j][0] *= a0; O[j][1] *= a0;
            O[j][2] *= a1; O[j][3] *= a1;
        }

        // O += P . V  (single fp16 MMA per step)
#pragma unroll
        for (int t = 0; t < 4; t++) {
            const uint32_t p0 = pack_h(S[2 * t][0],     S[2 * t][1]);
            const uint32_t p1 = pack_h(S[2 * t][2],     S[2 * t][3]);
            const uint32_t p2 = pack_h(S[2 * t + 1][0], S[2 * t + 1][1]);
            const uint32_t p3 = pack_h(S[2 * t + 1][2], S[2 * t + 1][3]);
#pragma unroll
            for (int j = 0; j < 8; j++) {
                const int lat = 8 * j + g;
                const uint32_t b0 = sV[lat][8 * t + c];
                const uint32_t b1 = sV[lat][8 * t + 4 + c];
                float* d = O[j];
                mma_f16(d[0], d[1], d[2], d[3], p0, p1, p2, p3, b0, b1);
            }
        }
    }

    // normalize + write y as fp16 hi/lo
    const float i0 = 1.f / l0;
    const float i1 = 1.f / l1;
#pragma unroll
    for (int j = 0; j < 8; j++) {
        const int col = 8 * j + 2 * c;
        uint32_t h2, l2;
        split_pack_h(O[j][0] * i0, O[j][1] * i0, h2, l2);
        *reinterpret_cast<uint32_t*>(Yh + base + (size_t)r0 * N_EMBD + col) = h2;
        *reinterpret_cast<uint32_t*>(Yl + base + (size_t)r0 * N_EMBD + col) = l2;
        split_pack_h(O[j][2] * i1, O[j][3] * i1, h2, l2);
        *reinterpret_cast<uint32_t*>(Yh + base + (size_t)r1 * N_EMBD + col) = h2;
        *reinterpret_cast<uint32_t*>(Yl + base + (size_t)r1 * N_EMBD + col) = l2;
    }
}

// ---------------------------------------------------------------------------
// Launcher. Inputs: x,Wq,bq,Wk,bk,Wv,bv,Wo,bo,Wc   (6 launches total)
// ---------------------------------------------------------------------------
extern "C" void kernel_launch(void* const* d_in, const int* in_sizes, int n_in,
                              void* d_out, int out_size)
{
    const float* x  = (const float*)d_in[0];
    const float* Wq = (const float*)d_in[1];
    const float* bq = (const float*)d_in[2];
    const float* Wk = (const float*)d_in[3];
    const float* bk = (const float*)d_in[4];
    const float* Wv = (const float*)d_in[5];
    const float* bv = (const float*)d_in[6];
    const float* Wo = (const float*)d_in[7];
    const float* bo = (const float*)d_in[8];
    const float* Wc = (const float*)d_in[9];
    float* out = (float*)d_out;

    float *pWqc, *pbqc;
    __half *pqkvh, *pqkvl, *pxh, *pxl, *pyh, *pyl, *pwt;
    cudaGetSymbolAddress((void**)&pWqc,  g_Wqc);
    cudaGetSymbolAddress((void**)&pbqc,  g_bqc);
    cudaGetSymbolAddress((void**)&pqkvh, g_qkvh);
    cudaGetSymbolAddress((void**)&pqkvl, g_qkvl);
    cudaGetSymbolAddress((void**)&pxh,   g_xs_hi);
    cudaGetSymbolAddress((void**)&pxl,   g_xs_lo);
    cudaGetSymbolAddress((void**)&pyh,   g_ys_hi);
    cudaGetSymbolAddress((void**)&pyl,   g_ys_lo);
    cudaGetSymbolAddress((void**)&pwt,   g_wt);

    const size_t MN = (size_t)MROWS * N_EMBD;

    cudaFuncSetAttribute(gemm_qkv_mma,
                         cudaFuncAttributeMaxDynamicSharedMemorySize, GEMM_SMEM);
    cudaFuncSetAttribute(gemm_out_mma,
                         cudaFuncAttributeMaxDynamicSharedMemorySize, GEMM_SMEM);

    // 1. Wqc build
    build_wqc<<<4096, 256>>>(Wq, Wc, bq, pWqc, pbqc);

    // 2. split x (fp16)
    const int n2x = MROWS * N_EMBD / 2;
    split2h<<<(n2x + 255) / 256, 256>>>(x, (__half2*)pxh, (__half2*)pxl, n2x);

    // 3. transpose all weights to [N][K] fp16
    const dim3 tg(N_EMBD / 32, N_EMBD / 32, 4);
    tsplit_all<<<tg, dim3(32, 8)>>>(pWqc, Wk, Wv, Wo, pwt);

    // 4. QKV projection (fp16x2; lo written only for qc)
    const dim3 gq(N_EMBD / 128, MROWS / 128, 3);
    gemm_qkv_mma<<<gq, 256, GEMM_SMEM>>>(pxh, pxl, pbqc, bk, bv, pqkvh, pqkvl);

    // 5. attention (fp16 MMAs; fp32 softmax)
    flash_mma<<<dim3(SEQ / 128, BATCH * N_HEADS), 256>>>(
        pqkvh, pqkvl,                    // Q hi/lo
        pqkvh + MN,                      // K (fp16)
        pqkvh + 2 * MN,                  // V (fp16)
        pyh, pyl);

    // 6. output projection (fp16x2)
    const dim3 gg(N_EMBD / 128, MROWS / 128);
    gemm_out_mma<<<gg, 256, GEMM_SMEM>>>(pyh, pyl, bo, out);
}

// round 13
// speedup vs baseline: 1.6635x; 1.1389x over previous
#include <cuda_runtime.h>
#include <cuda_bf16.h>
#include <cuda_fp16.h>
#include <cstdint>
#include <cstddef>

// ---------------------------------------------------------------------------
// LatentAttention v10: B=2, T=2048, n_embd=1024, heads=16, latent=64
//   - q-proj: fp16x2 (x split);  k/v-proj: single fp16 MMA
//   - flash: QK^T 1 MMA (q,k single fp16), PV 1 MMA, fp32 softmax
//   - out-proj: fp16x2 (y split)  [margin guard]
//   error budget: ~8 fp16-trunc terms x 2.4e-4  ->  ~6.5e-4  (gate 1e-3)
// ---------------------------------------------------------------------------

#define N_EMBD   1024
#define N_HEADS  16
#define LATENT   64
#define BATCH    2
#define SEQ      2048
#define MROWS    (BATCH * SEQ)          // 4096
#define KDIM     1024

// ------------------------- device scratch ----------------------------------
__device__ float  g_Wqc[N_EMBD * N_EMBD];
__device__ float  g_bqc[N_EMBD];
__device__ __half g_qkv[3 * MROWS * N_EMBD];    // [qc | k | v] fp16
__device__ __half g_xs_hi[MROWS * N_EMBD];
__device__ __half g_xs_lo[MROWS * N_EMBD];
__device__ __half g_ys_hi[MROWS * N_EMBD];
__device__ __half g_ys_lo[MROWS * N_EMBD];
__device__ __half g_wt[4][N_EMBD * N_EMBD];     // 0=Wqc 1=Wk 2=Wv 3=Wo, [N][K]

// ---------------------------------------------------------------------------
__global__ void build_wqc(const float* __restrict__ Wq,
                          const float* __restrict__ Wc,
                          const float* __restrict__ bq,
                          float* __restrict__ Wqc,
                          float* __restrict__ bqc)
{
    int idx = blockIdx.x * blockDim.x + threadIdx.x;
    int c   = idx >> 10;
    int col = idx & 1023;
    int h   = col >> 6;
    int l   = col & 63;
    const float* wrow = &Wq[(size_t)c * N_EMBD + h * LATENT];
    float s = 0.f;
#pragma unroll 8
    for (int d = 0; d < LATENT; d++)
        s += wrow[d] * Wc[d * LATENT + l];
    Wqc[idx] = s;
    if (c == 0) {
        float sb = 0.f;
#pragma unroll 8
        for (int d = 0; d < LATENT; d++)
            sb += bq[h * LATENT + d] * Wc[d * LATENT + l];
        bqc[col] = sb;
    }
}

__global__ void split2h(const float* __restrict__ src,
                        __half2* __restrict__ hi, __half2* __restrict__ lo,
                        int n2)
{
    int i = blockIdx.x * blockDim.x + threadIdx.x;
    if (i >= n2) return;
    const float2 v = reinterpret_cast<const float2*>(src)[i];
    __half h0 = __float2half_rn(v.x);
    __half h1 = __float2half_rn(v.y);
    __half l0 = __float2half_rn(v.x - __half2float(h0));
    __half l1 = __float2half_rn(v.y - __half2float(h1));
    hi[i] = __halves2half2(h0, h1);
    lo[i] = __halves2half2(l0, l1);
}

__global__ void tsplit_all(const float* __restrict__ W0,
                           const float* __restrict__ W1,
                           const float* __restrict__ W2,
                           const float* __restrict__ W3,
                           __half* __restrict__ T)
{
    __shared__ float t[32][33];
    const int z = blockIdx.z;
    const float* W = (z == 0) ? W0 : (z == 1) ? W1 : (z == 2) ? W2 : W3;
    __half* th = T + (size_t)z * N_EMBD * N_EMBD;

    const int tx = threadIdx.x, ty = threadIdx.y;
    const int n0 = blockIdx.x * 32, k0 = blockIdx.y * 32;
#pragma unroll
    for (int i = 0; i < 4; i++)
        t[ty + 8 * i][tx] = W[(size_t)(k0 + ty + 8 * i) * N_EMBD + n0 + tx];
    __syncthreads();
#pragma unroll
    for (int i = 0; i < 4; i++) {
        const int n = n0 + ty + 8 * i;
        const int k = k0 + tx;
        th[(size_t)n * KDIM + k] = __float2half_rn(t[tx][ty + 8 * i]);
    }
}

// ---------------------------------------------------------------------------
// primitives
// ---------------------------------------------------------------------------
__device__ __forceinline__
void mma_f16(float& d0, float& d1, float& d2, float& d3,
             uint32_t a0, uint32_t a1, uint32_t a2, uint32_t a3,
             uint32_t b0, uint32_t b1)
{
    asm volatile(
        "mma.sync.aligned.m16n8k16.row.col.f32.f16.f16.f32 "
        "{%0,%1,%2,%3}, {%4,%5,%6,%7}, {%8,%9}, {%0,%1,%2,%3};\n"
        : "+f"(d0), "+f"(d1), "+f"(d2), "+f"(d3)
        : "r"(a0), "r"(a1), "r"(a2), "r"(a3), "r"(b0), "r"(b1));
}

__device__ __forceinline__
void split_pack_h(float x, float y, uint32_t& hi, uint32_t& lo)
{
    __half2 h = __floats2half2_rn(x, y);
    __half2 l = __floats2half2_rn(x - __half2float(__low2half(h)),
                                  y - __half2float(__high2half(h)));
    hi = *reinterpret_cast<uint32_t*>(&h);
    lo = *reinterpret_cast<uint32_t*>(&l);
}

__device__ __forceinline__ uint32_t pack_h(float x, float y)
{
    __half2 h = __floats2half2_rn(x, y);
    return *reinterpret_cast<uint32_t*>(&h);
}

__device__ __forceinline__ uint32_t mul8h(uint32_t w)
{
    __half2 v = *reinterpret_cast<__half2*>(&w);
    v = __hmul2(v, __floats2half2_rn(0.125f, 0.125f));   // 2^-3 exact
    return *reinterpret_cast<uint32_t*>(&v);
}

__device__ __forceinline__ void cp16(uint32_t d, const void* s) {
    asm volatile("cp.async.cg.shared.global [%0], [%1], 16;" :: "r"(d), "l"(s));
}
__device__ __forceinline__ void cp_commit() {
    asm volatile("cp.async.commit_group;");
}
__device__ __forceinline__ void cp_wait1() {
    asm volatile("cp.async.wait_group 1;");
}
__device__ __forceinline__
void ldsm4(uint32_t& r0, uint32_t& r1, uint32_t& r2, uint32_t& r3, uint32_t a) {
    asm volatile("ldmatrix.sync.aligned.m8n8.x4.shared.b16 {%0,%1,%2,%3}, [%4];"
                 : "=r"(r0), "=r"(r1), "=r"(r2), "=r"(r3) : "r"(a));
}

// ---------------------------------------------------------------------------
// GEMM: 128x128 tile, BK=32, 8 warps (2m x 4n), 3-stage cp.async pipeline.
// two_terms: A = ah+al (2 MMAs/step);  else A = ah (1 MMA/step, skip Al load).
// ---------------------------------------------------------------------------
#define SMW 20
#define TST (128 * SMW)            // words per array
#define TSTG (3 * TST)             // words per stage (Ah, Al, B)
#define NST 3
#define GEMM_SMEM (NST * TSTG * 4) // 92160 bytes

template<bool SPLIT_OUT>
__device__ __forceinline__
void gemm2_body(const __half* __restrict__ Ah_, const __half* __restrict__ Al_,
                const __half* __restrict__ Bh_,
                const float* __restrict__ bias,
                float* __restrict__ C, __half* __restrict__ Ch,
                bool two_terms,
                int N, int K, int bx, int by)
{
    extern __shared__ uint32_t gsm[];
    const int tid    = threadIdx.x;
    const int lane   = tid & 31;
    const int wid    = tid >> 5;
    const int warp_m = wid >> 2;
    const int warp_n = wid & 3;
    const int m0     = by * 128;
    const int n0     = bx * 128;
    const int lg     = lane >> 2;
    const int lc     = lane & 3;
    const uint32_t sbase = (uint32_t)__cvta_generic_to_shared(gsm);

    float acc[4][4][4];
#pragma unroll
    for (int i = 0; i < 4; i++)
#pragma unroll
        for (int j = 0; j < 4; j++)
#pragma unroll
            for (int c = 0; c < 4; c++) acc[i][j][c] = 0.f;

    const int KT = K >> 5;               // 32

    auto load_stage = [&](int slot, int kb) {
        const uint32_t dst0 = sbase + (uint32_t)(slot * TSTG * 4);
#pragma unroll
        for (int arr = 0; arr < 3; arr++) {
            if (arr == 1 && !two_terms) continue;     // uniform skip
            const __half* src = (arr == 0) ? Ah_ : (arr == 1) ? Al_ : Bh_;
            const int rbase = (arr < 2) ? m0 : n0;
#pragma unroll
            for (int it = 0; it < 2; it++) {
                const int sub = tid + it * 256;      // 0..511
                const int row = sub >> 2;            // 0..127
                const int q   = sub & 3;             // 16B chunk
                cp16(dst0 + (uint32_t)((arr * TST + row * SMW + q * 4) * 4),
                     src + (size_t)(rbase + row) * K + kb + q * 8);
            }
        }
        cp_commit();
    };

    load_stage(0, 0);
    load_stage(1, 32);

    const int arow = lane & 15;
    const int acol = (lane & 16) ? 4 : 0;
    const int brow = (lane & 7) + ((lane & 16) ? 8 : 0);
    const int bcol = (lane & 8) ? 4 : 0;

    for (int kt = 0; kt < KT; kt++) {
        cp_wait1();
        __syncthreads();
        if (kt + 2 < KT) load_stage((kt + 2) % NST, (kt + 2) * 32);
        else             cp_commit();     // keep group accounting exact

        const int slot = kt % NST;
        const uint32_t st    = sbase + (uint32_t)(slot * TSTG * 4);
        const uint32_t offAh = st;
        const uint32_t offAl = st + TST * 4;
        const uint32_t offB  = st + 2 * TST * 4;

#pragma unroll
        for (int ks = 0; ks < 2; ks++) {
            const int kw = ks * 8;
            uint32_t bh[8];
#pragma unroll
            for (int jp = 0; jp < 2; jp++) {
                const int rB = warp_n * 32 + jp * 16 + brow;
                const uint32_t off = (uint32_t)((rB * SMW + kw + bcol) * 4);
                ldsm4(bh[jp*4+0], bh[jp*4+1], bh[jp*4+2], bh[jp*4+3], offB + off);
            }
#pragma unroll
            for (int i = 0; i < 4; i++) {
                const int rA = warp_m * 64 + i * 16 + arow;
                const uint32_t off = (uint32_t)((rA * SMW + kw + acol) * 4);
                uint32_t ah0, ah1, ah2, ah3;
                ldsm4(ah0, ah1, ah2, ah3, offAh + off);
#pragma unroll
                for (int j = 0; j < 4; j++) {
                    const int bi = (j >> 1) * 4 + (j & 1) * 2;
                    float* d = acc[i][j];
                    mma_f16(d[0], d[1], d[2], d[3],
                            ah0, ah1, ah2, ah3, bh[bi], bh[bi+1]);
                }
                if (two_terms) {
                    uint32_t al0, al1, al2, al3;
                    ldsm4(al0, al1, al2, al3, offAl + off);
#pragma unroll
                    for (int j = 0; j < 4; j++) {
                        const int bi = (j >> 1) * 4 + (j & 1) * 2;
                        float* d = acc[i][j];
                        mma_f16(d[0], d[1], d[2], d[3],
                                al0, al1, al2, al3, bh[bi], bh[bi+1]);
                    }
                }
            }
        }
    }

    // epilogue
#pragma unroll
    for (int j = 0; j < 4; j++) {
        const int cn = n0 + warp_n * 32 + j * 8 + 2 * lc;
        const float2 bb = *reinterpret_cast<const float2*>(&bias[cn]);
#pragma unroll
        for (int i = 0; i < 4; i++) {
            const int r = m0 + warp_m * 64 + i * 16 + lg;
            const float v0 = acc[i][j][0] + bb.x, v1 = acc[i][j][1] + bb.y;
            const float v2 = acc[i][j][2] + bb.x, v3 = acc[i][j][3] + bb.y;
            if (SPLIT_OUT) {
                *reinterpret_cast<uint32_t*>(Ch + (size_t)r * N + cn) =
                    pack_h(v0, v1);
                *reinterpret_cast<uint32_t*>(Ch + (size_t)(r + 8) * N + cn) =
                    pack_h(v2, v3);
            } else {
                *reinterpret_cast<float2*>(&C[(size_t)r * N + cn]) =
                    make_float2(v0, v1);
                *reinterpret_cast<float2*>(&C[(size_t)(r + 8) * N + cn]) =
                    make_float2(v2, v3);
            }
        }
    }
}

__global__ __launch_bounds__(256)
void gemm_qkv_mma(const __half* __restrict__ xh, const __half* __restrict__ xl,
                  const float* __restrict__ bqc,
                  const float* __restrict__ bk,
                  const float* __restrict__ bv,
                  __half* __restrict__ qkv)
{
    const int z = blockIdx.z;
    const float* b = (z == 0) ? bqc : (z == 1) ? bk : bv;
    gemm2_body<true>(xh, xl, g_wt[z], b, nullptr,
                     qkv + (size_t)z * MROWS * N_EMBD,
                     /*two_terms=*/(z == 0),
                     N_EMBD, KDIM, blockIdx.x, blockIdx.y);
}

__global__ __launch_bounds__(256)
void gemm_out_mma(const __half* __restrict__ yh, const __half* __restrict__ yl,
                  const float* __restrict__ bo, float* __restrict__ C)
{
    gemm2_body<false>(yh, yl, g_wt[3], bo, C, nullptr, /*two_terms=*/true,
                      N_EMBD, KDIM, blockIdx.x, blockIdx.y);
}

// ---------------------------------------------------------------------------
// Flash attention v10 — single fp16 MMA each for QK^T and PV; fp32 softmax.
// 256 threads = 8 warps; 128 q-rows (16/warp), 64-key tiles.
// ---------------------------------------------------------------------------
#define FW 36

__global__ __launch_bounds__(256)
void flash_mma(const __half* __restrict__ Qg,
               const __half* __restrict__ Kg, const __half* __restrict__ Vg,
               __half* __restrict__ Yh, __half* __restrict__ Yl)
{
    __shared__ uint32_t sK[64][FW];   // [key][lat-pair]  fp16
    __shared__ uint32_t sV[64][FW];   // [lat][key-pair]  fp16 (transposed)

    const int tid  = threadIdx.x;
    const int lane = tid & 31;
    const int wid  = tid >> 5;
    const int g    = lane >> 2;
    const int c    = lane & 3;
    const int qb   = gridDim.x - 1 - blockIdx.x;   // long blocks first
    const int bh   = blockIdx.y;
    const int b    = bh >> 4;
    const int h    = bh & 15;
    const size_t base = (size_t)b * SEQ * N_EMBD + (size_t)h * LATENT;

    const int r0 = qb * 128 + wid * 16 + g;
    const int r1 = r0 + 8;

    // Q fragments (fp16), 1/8 scale folded in (exact power of 2)
    uint32_t qf[4][4];
#pragma unroll
    for (int ks = 0; ks < 4; ks++) {
        const int k0a = 16 * ks + 2 * c;
        const size_t e0 = base + (size_t)r0 * N_EMBD + k0a;
        const size_t e1 = base + (size_t)r1 * N_EMBD + k0a;
        qf[ks][0] = mul8h(*reinterpret_cast<const uint32_t*>(Qg + e0));
        qf[ks][1] = mul8h(*reinterpret_cast<const uint32_t*>(Qg + e1));
        qf[ks][2] = mul8h(*reinterpret_cast<const uint32_t*>(Qg + e0 + 8));
        qf[ks][3] = mul8h(*reinterpret_cast<const uint32_t*>(Qg + e1 + 8));
    }

    float m0 = -1e30f, m1 = -1e30f, l0 = 0.f, l1 = 0.f;
    float O[8][4];
#pragma unroll
    for (int j = 0; j < 8; j++)
#pragma unroll
        for (int t = 0; t < 4; t++) O[j][t] = 0.f;

    const int jmax = 2 * qb + 1;
    for (int jb = 0; jb <= jmax; jb++) {
        __syncthreads();
        // load K (natural) + V (transposed) fp16 tiles
#pragma unroll
        for (int it = 0; it < 4; it++) {
            const int idx = tid + it * 256;        // 0..1023
            const int key = idx >> 4;              // 0..63
            const int wq  = idx & 15;              // 4-lat group
            const size_t ge = base + (size_t)(jb * 64 + key) * N_EMBD + wq * 4;
            *reinterpret_cast<uint2*>(&sK[key][wq * 2]) =
                *reinterpret_cast<const uint2*>(Kg + ge);
            const uint2 vv = *reinterpret_cast<const uint2*>(Vg + ge);
            const __half* ve = reinterpret_cast<const __half*>(&vv);
            __half* vp = reinterpret_cast<__half*>(&sV[0][0]);
#pragma unroll
            for (int e = 0; e < 4; e++)
                vp[(wq * 4 + e) * (2 * FW) + key] = ve[e];
        }
        __syncthreads();

        // S = Q . K^T (1 fp16 MMA per step)
        float S[8][4];
#pragma unroll
        for (int j = 0; j < 8; j++)
#pragma unroll
            for (int t = 0; t < 4; t++) S[j][t] = 0.f;

#pragma unroll
        for (int ks = 0; ks < 4; ks++) {
#pragma unroll
            for (int j = 0; j < 8; j++) {
                const int key = 8 * j + g;
                const uint32_t b0 = sK[key][8 * ks + c];
                const uint32_t b1 = sK[key][8 * ks + 4 + c];
                mma_f16(S[j][0], S[j][1], S[j][2], S[j][3],
                        qf[ks][0], qf[ks][1], qf[ks][2], qf[ks][3], b0, b1);
            }
        }

        // causal mask
        if (jb >= 2 * qb) {
#pragma unroll
            for (int j = 0; j < 8; j++) {
                const int col = jb * 64 + 8 * j + 2 * c;
                if (col     > r0) S[j][0] = -1e30f;
                if (col + 1 > r0) S[j][1] = -1e30f;
                if (col     > r1) S[j][2] = -1e30f;
                if (col + 1 > r1) S[j][3] = -1e30f;
            }
        }

        // online softmax (fp32)
        float mx0 = -1e30f, mx1 = -1e30f;
#pragma unroll
        for (int j = 0; j < 8; j++) {
            mx0 = fmaxf(mx0, fmaxf(S[j][0], S[j][1]));
            mx1 = fmaxf(mx1, fmaxf(S[j][2], S[j][3]));
        }
        mx0 = fmaxf(mx0, __shfl_xor_sync(0xffffffffu, mx0, 1));
        mx0 = fmaxf(mx0, __shfl_xor_sync(0xffffffffu, mx0, 2));
        mx1 = fmaxf(mx1, __shfl_xor_sync(0xffffffffu, mx1, 1));
        mx1 = fmaxf(mx1, __shfl_xor_sync(0xffffffffu, mx1, 2));

        const float mn0 = fmaxf(m0, mx0);
        const float mn1 = fmaxf(m1, mx1);
        const float a0  = __expf(m0 - mn0);
        const float a1  = __expf(m1 - mn1);
        m0 = mn0; m1 = mn1;

        float rs0 = 0.f, rs1 = 0.f;
#pragma unroll
        for (int j = 0; j < 8; j++) {
            S[j][0] = __expf(S[j][0] - mn0);
            S[j][1] = __expf(S[j][1] - mn0);
            S[j][2] = __expf(S[j][2] - mn1);
            S[j][3] = __expf(S[j][3] - mn1);
            rs0 += S[j][0] + S[j][1];
            rs1 += S[j][2] + S[j][3];
        }
        rs0 += __shfl_xor_sync(0xffffffffu, rs0, 1);
        rs0 += __shfl_xor_sync(0xffffffffu, rs0, 2);
        rs1 += __shfl_xor_sync(0xffffffffu, rs1, 1);
        rs1 += __shfl_xor_sync(0xffffffffu, rs1, 2);
        l0 = l0 * a0 + rs0;
        l1 = l1 * a1 + rs1;

#pragma unroll
        for (int j = 0; j < 8; j++) {
            O[j][0] *= a0; O[j][1] *= a0;
            O[j][2] *= a1; O[j][3] *= a1;
        }

        // O += P . V  (single fp16 MMA per step)
#pragma unroll
        for (int t = 0; t < 4; t++) {
            const uint32_t p0 = pack_h(S[2 * t][0],     S[2 * t][1]);
            const uint32_t p1 = pack_h(S[2 * t][2],     S[2 * t][3]);
            const uint32_t p2 = pack_h(S[2 * t + 1][0], S[2 * t + 1][1]);
            const uint32_t p3 = pack_h(S[2 * t + 1][2], S[2 * t + 1][3]);
#pragma unroll
            for (int j = 0; j < 8; j++) {
                const int lat = 8 * j + g;
                const uint32_t b0 = sV[lat][8 * t + c];
                const uint32_t b1 = sV[lat][8 * t + 4 + c];
                mma_f16(O[j][0], O[j][1], O[j][2], O[j][3], p0, p1, p2, p3, b0, b1);
            }
        }
    }

    // normalize + write y as fp16 hi/lo (y keeps split: out-proj is 2-term)
    const float i0 = 1.f / l0;
    const float i1 = 1.f / l1;
#pragma unroll
    for (int j = 0; j < 8; j++) {
        const int col = 8 * j + 2 * c;
        uint32_t h2, l2;
        split_pack_h(O[j][0] * i0, O[j][1] * i0, h2, l2);
        *reinterpret_cast<uint32_t*>(Yh + base + (size_t)r0 * N_EMBD + col) = h2;
        *reinterpret_cast<uint32_t*>(Yl + base + (size_t)r0 * N_EMBD + col) = l2;
        split_pack_h(O[j][2] * i1, O[j][3] * i1, h2, l2);
        *reinterpret_cast<uint32_t*>(Yh + base + (size_t)r1 * N_EMBD + col) = h2;
        *reinterpret_cast<uint32_t*>(Yl + base + (size_t)r1 * N_EMBD + col) = l2;
    }
}

// ---------------------------------------------------------------------------
// Launcher. Inputs: x,Wq,bq,Wk,bk,Wv,bv,Wo,bo,Wc   (6 launches total)
// ---------------------------------------------------------------------------
extern "C" void kernel_launch(void* const* d_in, const int* in_sizes, int n_in,
                              void* d_out, int out_size)
{
    const float* x  = (const float*)d_in[0];
    const float* Wq = (const float*)d_in[1];
    const float* bq = (const float*)d_in[2];
    const float* Wk = (const float*)d_in[3];
    const float* bk = (const float*)d_in[4];
    const float* Wv = (const float*)d_in[5];
    const float* bv = (const float*)d_in[6];
    const float* Wo = (const float*)d_in[7];
    const float* bo = (const float*)d_in[8];
    const float* Wc = (const float*)d_in[9];
    float* out = (float*)d_out;

    float *pWqc, *pbqc;
    __half *pqkv, *pxh, *pxl, *pyh, *pyl, *pwt;
    cudaGetSymbolAddress((void**)&pWqc, g_Wqc);
    cudaGetSymbolAddress((void**)&pbqc, g_bqc);
    cudaGetSymbolAddress((void**)&pqkv, g_qkv);
    cudaGetSymbolAddress((void**)&pxh,  g_xs_hi);
    cudaGetSymbolAddress((void**)&pxl,  g_xs_lo);
    cudaGetSymbolAddress((void**)&pyh,  g_ys_hi);
    cudaGetSymbolAddress((void**)&pyl,  g_ys_lo);
    cudaGetSymbolAddress((void**)&pwt,  g_wt);

    const size_t MN = (size_t)MROWS * N_EMBD;

    cudaFuncSetAttribute(gemm_qkv_mma,
                         cudaFuncAttributeMaxDynamicSharedMemorySize, GEMM_SMEM);
    cudaFuncSetAttribute(gemm_out_mma,
                         cudaFuncAttributeMaxDynamicSharedMemorySize, GEMM_SMEM);

    // 1. Wqc build
    build_wqc<<<4096, 256>>>(Wq, Wc, bq, pWqc, pbqc);

    // 2. split x (fp16)
    const int n2x = MROWS * N_EMBD / 2;
    split2h<<<(n2x + 255) / 256, 256>>>(x, (__half2*)pxh, (__half2*)pxl, n2x);

    // 3. transpose all weights to [N][K] fp16
    const dim3 tg(N_EMBD / 32, N_EMBD / 32, 4);
    tsplit_all<<<tg, dim3(32, 8)>>>(pWqc, Wk, Wv, Wo, pwt);

    // 4. QKV projection (q: 2-term, k/v: 1-term; fp16 outputs)
    const dim3 gq(N_EMBD / 128, MROWS / 128, 3);
    gemm_qkv_mma<<<gq, 256, GEMM_SMEM>>>(pxh, pxl, pbqc, bk, bv, pqkv);

    // 5. attention (single-MMA QK and PV; fp32 softmax)
    flash_mma<<<dim3(SEQ / 128, BATCH * N_HEADS), 256>>>(
        pqkv,                            // Q
        pqkv + MN,                       // K
        pqkv + 2 * MN,                   // V
        pyh, pyl);

    // 6. output projection (fp16x2)
    const dim3 gg(N_EMBD / 128, MROWS / 128);
    gemm_out_mma<<<gg, 256, GEMM_SMEM>>>(pyh, pyl, bo, out);
}

// round 14
// speedup vs baseline: 1.7936x; 1.0782x over previous
#include <cuda_runtime.h>
#include <cuda_bf16.h>
#include <cuda_fp16.h>
#include <cstdint>
#include <cstddef>

// ---------------------------------------------------------------------------
// LatentAttention v11: B=2, T=2048, n_embd=1024, heads=16, latent=64
//   - GEMMs: fp16 (q-proj 2-term, k/v/out 1-term), 2-stage pipeline,
//     2 CTAs/SM (61KB smem), ldmatrix + cp.async
//   - flash: single fp16 MMA QK^T / PV, fp32 softmax, register-prefetched
//     K/V tiles; y written fp16 hi only
// ---------------------------------------------------------------------------

#define N_EMBD   1024
#define N_HEADS  16
#define LATENT   64
#define BATCH    2
#define SEQ      2048
#define MROWS    (BATCH * SEQ)          // 4096
#define KDIM     1024

// ------------------------- device scratch ----------------------------------
__device__ float  g_Wqc[N_EMBD * N_EMBD];
__device__ float  g_bqc[N_EMBD];
__device__ __half g_qkv[3 * MROWS * N_EMBD];    // [qc | k | v] fp16
__device__ __half g_xs_hi[MROWS * N_EMBD];
__device__ __half g_xs_lo[MROWS * N_EMBD];
__device__ __half g_ys  [MROWS * N_EMBD];       // y fp16 (single plane)
__device__ __half g_wt[4][N_EMBD * N_EMBD];     // 0=Wqc 1=Wk 2=Wv 3=Wo, [N][K]

// ---------------------------------------------------------------------------
__global__ void build_wqc(const float* __restrict__ Wq,
                          const float* __restrict__ Wc,
                          const float* __restrict__ bq,
                          float* __restrict__ Wqc,
                          float* __restrict__ bqc)
{
    int idx = blockIdx.x * blockDim.x + threadIdx.x;
    int c   = idx >> 10;
    int col = idx & 1023;
    int h   = col >> 6;
    int l   = col & 63;
    const float* wrow = &Wq[(size_t)c * N_EMBD + h * LATENT];
    float s = 0.f;
#pragma unroll 8
    for (int d = 0; d < LATENT; d++)
        s += wrow[d] * Wc[d * LATENT + l];
    Wqc[idx] = s;
    if (c == 0) {
        float sb = 0.f;
#pragma unroll 8
        for (int d = 0; d < LATENT; d++)
            sb += bq[h * LATENT + d] * Wc[d * LATENT + l];
        bqc[col] = sb;
    }
}

__global__ void split2h(const float* __restrict__ src,
                        __half2* __restrict__ hi, __half2* __restrict__ lo,
                        int n2)
{
    int i = blockIdx.x * blockDim.x + threadIdx.x;
    if (i >= n2) return;
    const float2 v = reinterpret_cast<const float2*>(src)[i];
    __half h0 = __float2half_rn(v.x);
    __half h1 = __float2half_rn(v.y);
    __half l0 = __float2half_rn(v.x - __half2float(h0));
    __half l1 = __float2half_rn(v.y - __half2float(h1));
    hi[i] = __halves2half2(h0, h1);
    lo[i] = __halves2half2(l0, l1);
}

__global__ void tsplit_all(const float* __restrict__ W0,
                           const float* __restrict__ W1,
                           const float* __restrict__ W2,
                           const float* __restrict__ W3,
                           __half* __restrict__ T)
{
    __shared__ float t[32][33];
    const int z = blockIdx.z;
    const float* W = (z == 0) ? W0 : (z == 1) ? W1 : (z == 2) ? W2 : W3;
    __half* th = T + (size_t)z * N_EMBD * N_EMBD;

    const int tx = threadIdx.x, ty = threadIdx.y;
    const int n0 = blockIdx.x * 32, k0 = blockIdx.y * 32;
#pragma unroll
    for (int i = 0; i < 4; i++)
        t[ty + 8 * i][tx] = W[(size_t)(k0 + ty + 8 * i) * N_EMBD + n0 + tx];
    __syncthreads();
#pragma unroll
    for (int i = 0; i < 4; i++) {
        const int n = n0 + ty + 8 * i;
        const int k = k0 + tx;
        th[(size_t)n * KDIM + k] = __float2half_rn(t[tx][ty + 8 * i]);
    }
}

// ---------------------------------------------------------------------------
// primitives
// ---------------------------------------------------------------------------
__device__ __forceinline__
void mma_f16(float& d0, float& d1, float& d2, float& d3,
             uint32_t a0, uint32_t a1, uint32_t a2, uint32_t a3,
             uint32_t b0, uint32_t b1)
{
    asm volatile(
        "mma.sync.aligned.m16n8k16.row.col.f32.f16.f16.f32 "
        "{%0,%1,%2,%3}, {%4,%5,%6,%7}, {%8,%9}, {%0,%1,%2,%3};\n"
        : "+f"(d0), "+f"(d1), "+f"(d2), "+f"(d3)
        : "r"(a0), "r"(a1), "r"(a2), "r"(a3), "r"(b0), "r"(b1));
}

__device__ __forceinline__ uint32_t pack_h(float x, float y)
{
    __half2 h = __floats2half2_rn(x, y);
    return *reinterpret_cast<uint32_t*>(&h);
}

__device__ __forceinline__ uint32_t mul8h(uint32_t w)
{
    __half2 v = *reinterpret_cast<__half2*>(&w);
    v = __hmul2(v, __floats2half2_rn(0.125f, 0.125f));   // 2^-3 exact
    return *reinterpret_cast<uint32_t*>(&v);
}

__device__ __forceinline__ void cp16(uint32_t d, const void* s) {
    asm volatile("cp.async.cg.shared.global [%0], [%1], 16;" :: "r"(d), "l"(s));
}
__device__ __forceinline__ void cp_commit() {
    asm volatile("cp.async.commit_group;");
}
__device__ __forceinline__ void cp_wait1() {
    asm volatile("cp.async.wait_group 1;");
}
__device__ __forceinline__
void ldsm4(uint32_t& r0, uint32_t& r1, uint32_t& r2, uint32_t& r3, uint32_t a) {
    asm volatile("ldmatrix.sync.aligned.m8n8.x4.shared.b16 {%0,%1,%2,%3}, [%4];"
                 : "=r"(r0), "=r"(r1), "=r"(r2), "=r"(r3) : "r"(a));
}

// ---------------------------------------------------------------------------
// GEMM: 128x128 tile, BK=32, 8 warps (2m x 4n), 2-stage cp.async pipeline,
// 2 CTAs/SM.  two_terms: A = ah+al (2 MMAs/step) else 1 MMA/step.
// ---------------------------------------------------------------------------
#define SMW 20
#define TST (128 * SMW)            // words per array
#define TSTG (3 * TST)             // words per stage (Ah, Al, B)
#define GEMM_SMEM (2 * TSTG * 4)   // 61440 bytes -> 2 CTAs/SM

template<bool SPLIT_OUT>
__device__ __forceinline__
void gemm2_body(const __half* __restrict__ Ah_, const __half* __restrict__ Al_,
                const __half* __restrict__ Bh_,
                const float* __restrict__ bias,
                float* __restrict__ C, __half* __restrict__ Ch,
                bool two_terms,
                int N, int K, int bx, int by)
{
    extern __shared__ uint32_t gsm[];
    const int tid    = threadIdx.x;
    const int lane   = tid & 31;
    const int wid    = tid >> 5;
    const int warp_m = wid >> 2;
    const int warp_n = wid & 3;
    const int m0     = by * 128;
    const int n0     = bx * 128;
    const int lg     = lane >> 2;
    const int lc     = lane & 3;
    const uint32_t sbase = (uint32_t)__cvta_generic_to_shared(gsm);

    float acc[4][4][4];
#pragma unroll
    for (int i = 0; i < 4; i++)
#pragma unroll
        for (int j = 0; j < 4; j++)
#pragma unroll
            for (int c = 0; c < 4; c++) acc[i][j][c] = 0.f;

    const int KT = K >> 5;               // 32

    auto load_stage = [&](int slot, int kb) {
        const uint32_t dst0 = sbase + (uint32_t)(slot * TSTG * 4);
#pragma unroll
        for (int arr = 0; arr < 3; arr++) {
            if (arr == 1 && !two_terms) continue;     // uniform skip
            const __half* src = (arr == 0) ? Ah_ : (arr == 1) ? Al_ : Bh_;
            const int rbase = (arr < 2) ? m0 : n0;
#pragma unroll
            for (int it = 0; it < 2; it++) {
                const int sub = tid + it * 256;      // 0..511
                const int row = sub >> 2;            // 0..127
                const int q   = sub & 3;             // 16B chunk
                cp16(dst0 + (uint32_t)((arr * TST + row * SMW + q * 4) * 4),
                     src + (size_t)(rbase + row) * K + kb + q * 8);
            }
        }
        cp_commit();
    };

    load_stage(0, 0);
    load_stage(1, 32);

    const int arow = lane & 15;
    const int acol = (lane & 16) ? 4 : 0;
    const int brow = (lane & 7) + ((lane & 16) ? 8 : 0);
    const int bcol = (lane & 8) ? 4 : 0;

    for (int kt = 0; kt < KT; kt++) {
        cp_wait1();                       // stage kt resident
        __syncthreads();

        const int slot = kt & 1;
        const uint32_t st    = sbase + (uint32_t)(slot * TSTG * 4);
        const uint32_t offAh = st;
        const uint32_t offAl = st + TST * 4;
        const uint32_t offB  = st + 2 * TST * 4;

#pragma unroll
        for (int ks = 0; ks < 2; ks++) {
            const int kw = ks * 8;
            uint32_t bh[8];
#pragma unroll
            for (int jp = 0; jp < 2; jp++) {
                const int rB = warp_n * 32 + jp * 16 + brow;
                const uint32_t off = (uint32_t)((rB * SMW + kw + bcol) * 4);
                ldsm4(bh[jp*4+0], bh[jp*4+1], bh[jp*4+2], bh[jp*4+3], offB + off);
            }
#pragma unroll
            for (int i = 0; i < 4; i++) {
                const int rA = warp_m * 64 + i * 16 + arow;
                const uint32_t off = (uint32_t)((rA * SMW + kw + acol) * 4);
                uint32_t ah0, ah1, ah2, ah3;
                ldsm4(ah0, ah1, ah2, ah3, offAh + off);
#pragma unroll
                for (int j = 0; j < 4; j++) {
                    const int bi = (j >> 1) * 4 + (j & 1) * 2;
                    float* d = acc[i][j];
                    mma_f16(d[0], d[1], d[2], d[3],
                            ah0, ah1, ah2, ah3, bh[bi], bh[bi+1]);
                }
                if (two_terms) {
                    uint32_t al0, al1, al2, al3;
                    ldsm4(al0, al1, al2, al3, offAl + off);
#pragma unroll
                    for (int j = 0; j < 4; j++) {
                        const int bi = (j >> 1) * 4 + (j & 1) * 2;
                        float* d = acc[i][j];
                        mma_f16(d[0], d[1], d[2], d[3],
                                al0, al1, al2, al3, bh[bi], bh[bi+1]);
                    }
                }
            }
        }

        __syncthreads();                  // compute on slot done; safe to refill
        if (kt + 2 < KT) load_stage(slot, (kt + 2) * 32);
        else             cp_commit();     // keep group accounting exact
    }

    // epilogue
#pragma unroll
    for (int j = 0; j < 4; j++) {
        const int cn = n0 + warp_n * 32 + j * 8 + 2 * lc;
        const float2 bb = *reinterpret_cast<const float2*>(&bias[cn]);
#pragma unroll
        for (int i = 0; i < 4; i++) {
            const int r = m0 + warp_m * 64 + i * 16 + lg;
            const float v0 = acc[i][j][0] + bb.x, v1 = acc[i][j][1] + bb.y;
            const float v2 = acc[i][j][2] + bb.x, v3 = acc[i][j][3] + bb.y;
            if (SPLIT_OUT) {
                *reinterpret_cast<uint32_t*>(Ch + (size_t)r * N + cn) =
                    pack_h(v0, v1);
                *reinterpret_cast<uint32_t*>(Ch + (size_t)(r + 8) * N + cn) =
                    pack_h(v2, v3);
            } else {
                *reinterpret_cast<float2*>(&C[(size_t)r * N + cn]) =
                    make_float2(v0, v1);
                *reinterpret_cast<float2*>(&C[(size_t)(r + 8) * N + cn]) =
                    make_float2(v2, v3);
            }
        }
    }
}

__global__ __launch_bounds__(256, 2)
void gemm_qkv_mma(const __half* __restrict__ xh, const __half* __restrict__ xl,
                  const float* __restrict__ bqc,
                  const float* __restrict__ bk,
                  const float* __restrict__ bv,
                  __half* __restrict__ qkv)
{
    const int z = blockIdx.z;
    const float* b = (z == 0) ? bqc : (z == 1) ? bk : bv;
    gemm2_body<true>(xh, xl, g_wt[z], b, nullptr,
                     qkv + (size_t)z * MROWS * N_EMBD,
                     /*two_terms=*/(z == 0),
                     N_EMBD, KDIM, blockIdx.x, blockIdx.y);
}

__global__ __launch_bounds__(256, 2)
void gemm_out_mma(const __half* __restrict__ y,
                  const float* __restrict__ bo, float* __restrict__ C)
{
    gemm2_body<false>(y, nullptr, g_wt[3], bo, C, nullptr, /*two_terms=*/false,
                      N_EMBD, KDIM, blockIdx.x, blockIdx.y);
}

// ---------------------------------------------------------------------------
// Flash attention v11 — single fp16 MMA QK^T/PV; fp32 softmax; K/V tiles
// software-pipelined through registers (LDG issued before compute phase).
// 256 threads = 8 warps; 128 q-rows (16/warp), 64-key tiles.
// ---------------------------------------------------------------------------
#define FW 36

__global__ __launch_bounds__(256)
void flash_mma(const __half* __restrict__ Qg,
               const __half* __restrict__ Kg, const __half* __restrict__ Vg,
               __half* __restrict__ Yg)
{
    __shared__ uint32_t sK[64][FW];   // [key][lat-pair]  fp16
    __shared__ uint32_t sV[64][FW];   // [lat][key-pair]  fp16 (transposed)

    const int tid  = threadIdx.x;
    const int lane = tid & 31;
    const int wid  = tid >> 5;
    const int g    = lane >> 2;
    const int c    = lane & 3;
    const int qb   = gridDim.x - 1 - blockIdx.x;   // long blocks first
    const int bh   = blockIdx.y;
    const int b    = bh >> 4;
    const int h    = bh & 15;
    const size_t base = (size_t)b * SEQ * N_EMBD + (size_t)h * LATENT;

    const int r0 = qb * 128 + wid * 16 + g;
    const int r1 = r0 + 8;

    // per-thread load coordinates (4 jobs of 256 threads covering 64x64 tile)
    int lkey[4], lwq[4];
#pragma unroll
    for (int it = 0; it < 4; it++) {
        const int idx = tid + it * 256;
        lkey[it] = idx >> 4;
        lwq[it]  = idx & 15;
    }

    // store one (K,V) register set into smem (V transposed)
    auto store_tile = [&](const uint2* kvr, const uint2* vvr) {
#pragma unroll
        for (int it = 0; it < 4; it++) {
            *reinterpret_cast<uint2*>(&sK[lkey[it]][lwq[it] * 2]) = kvr[it];
            const __half* ve = reinterpret_cast<const __half*>(&vvr[it]);
            __half* vp = reinterpret_cast<__half*>(&sV[0][0]);
#pragma unroll
            for (int e = 0; e < 4; e++)
                vp[(lwq[it] * 4 + e) * (2 * FW) + lkey[it]] = ve[e];
        }
    };

    // Q fragments (fp16), 1/8 scale folded in (exact power of 2)
    uint32_t qf[4][4];
#pragma unroll
    for (int ks = 0; ks < 4; ks++) {
        const int k0a = 16 * ks + 2 * c;
        const size_t e0 = base + (size_t)r0 * N_EMBD + k0a;
        const size_t e1 = base + (size_t)r1 * N_EMBD + k0a;
        qf[ks][0] = mul8h(*reinterpret_cast<const uint32_t*>(Qg + e0));
        qf[ks][1] = mul8h(*reinterpret_cast<const uint32_t*>(Qg + e1));
        qf[ks][2] = mul8h(*reinterpret_cast<const uint32_t*>(Qg + e0 + 8));
        qf[ks][3] = mul8h(*reinterpret_cast<const uint32_t*>(Qg + e1 + 8));
    }

    // preload tile 0
    {
        uint2 kvr[4], vvr[4];
#pragma unroll
        for (int it = 0; it < 4; it++) {
            const size_t ge = base + (size_t)lkey[it] * N_EMBD + lwq[it] * 4;
            kvr[it] = *reinterpret_cast<const uint2*>(Kg + ge);
            vvr[it] = *reinterpret_cast<const uint2*>(Vg + ge);
        }
        store_tile(kvr, vvr);
    }
    __syncthreads();

    float m0 = -1e30f, m1 = -1e30f, l0 = 0.f, l1 = 0.f;
    float O[8][4];
#pragma unroll
    for (int j = 0; j < 8; j++)
#pragma unroll
        for (int t = 0; t < 4; t++) O[j][t] = 0.f;

    const int jmax = 2 * qb + 1;
    for (int jb = 0; jb <= jmax; jb++) {
        // prefetch next tile into registers (hidden under compute)
        uint2 kvr[4], vvr[4];
        const bool has_next = (jb < jmax);
        if (has_next) {
#pragma unroll
            for (int it = 0; it < 4; it++) {
                const size_t ge = base +
                    (size_t)((jb + 1) * 64 + lkey[it]) * N_EMBD + lwq[it] * 4;
                kvr[it] = *reinterpret_cast<const uint2*>(Kg + ge);
                vvr[it] = *reinterpret_cast<const uint2*>(Vg + ge);
            }
        }

        // S = Q . K^T (1 fp16 MMA per step)
        float S[8][4];
#pragma unroll
        for (int j = 0; j < 8; j++)
#pragma unroll
            for (int t = 0; t < 4; t++) S[j][t] = 0.f;

#pragma unroll
        for (int ks = 0; ks < 4; ks++) {
#pragma unroll
            for (int j = 0; j < 8; j++) {
                const int key = 8 * j + g;
                const uint32_t b0 = sK[key][8 * ks + c];
                const uint32_t b1 = sK[key][8 * ks + 4 + c];
                mma_f16(S[j][0], S[j][1], S[j][2], S[j][3],
                        qf[ks][0], qf[ks][1], qf[ks][2], qf[ks][3], b0, b1);
            }
        }

        // causal mask
        if (jb >= 2 * qb) {
#pragma unroll
            for (int j = 0; j < 8; j++) {
                const int col = jb * 64 + 8 * j + 2 * c;
                if (col     > r0) S[j][0] = -1e30f;
                if (col + 1 > r0) S[j][1] = -1e30f;
                if (col     > r1) S[j][2] = -1e30f;
                if (col + 1 > r1) S[j][3] = -1e30f;
            }
        }

        // online softmax (fp32)
        float mx0 = -1e30f, mx1 = -1e30f;
#pragma unroll
        for (int j = 0; j < 8; j++) {
            mx0 = fmaxf(mx0, fmaxf(S[j][0], S[j][1]));
            mx1 = fmaxf(mx1, fmaxf(S[j][2], S[j][3]));
        }
        mx0 = fmaxf(mx0, __shfl_xor_sync(0xffffffffu, mx0, 1));
        mx0 = fmaxf(mx0, __shfl_xor_sync(0xffffffffu, mx0, 2));
        mx1 = fmaxf(mx1, __shfl_xor_sync(0xffffffffu, mx1, 1));
        mx1 = fmaxf(mx1, __shfl_xor_sync(0xffffffffu, mx1, 2));

        const float mn0 = fmaxf(m0, mx0);
        const float mn1 = fmaxf(m1, mx1);
        const float a0  = __expf(m0 - mn0);
        const float a1  = __expf(m1 - mn1);
        m0 = mn0; m1 = mn1;

        float rs0 = 0.f, rs1 = 0.f;
#pragma unroll
        for (int j = 0; j < 8; j++) {
            S[j][0] = __expf(S[j][0] - mn0);
            S[j][1] = __expf(S[j][1] - mn0);
            S[j][2] = __expf(S[j][2] - mn1);
            S[j][3] = __expf(S[j][3] - mn1);
            rs0 += S[j][0] + S[j][1];
            rs1 += S[j][2] + S[j][3];
        }
        rs0 += __shfl_xor_sync(0xffffffffu, rs0, 1);
        rs0 += __shfl_xor_sync(0xffffffffu, rs0, 2);
        rs1 += __shfl_xor_sync(0xffffffffu, rs1, 1);
        rs1 += __shfl_xor_sync(0xffffffffu, rs1, 2);
        l0 = l0 * a0 + rs0;
        l1 = l1 * a1 + rs1;

#pragma unroll
        for (int j = 0; j < 8; j++) {
            O[j][0] *= a0; O[j][1] *= a0;
            O[j][2] *= a1; O[j][3] *= a1;
        }

        // O += P . V  (single fp16 MMA per step)
#pragma unroll
        for (int t = 0; t < 4; t++) {
            const uint32_t p0 = pack_h(S[2 * t][0],     S[2 * t][1]);
            const uint32_t p1 = pack_h(S[2 * t][2],     S[2 * t][3]);
            const uint32_t p2 = pack_h(S[2 * t + 1][0], S[2 * t + 1][1]);
            const uint32_t p3 = pack_h(S[2 * t + 1][2], S[2 * t + 1][3]);
#pragma unroll
            for (int j = 0; j < 8; j++) {
                const int lat = 8 * j + g;
                const uint32_t b0 = sV[lat][8 * t + c];
                const uint32_t b1 = sV[lat][8 * t + 4 + c];
                mma_f16(O[j][0], O[j][1], O[j][2], O[j][3], p0, p1, p2, p3, b0, b1);
            }
        }

        if (has_next) {
            __syncthreads();           // all reads of sK/sV for jb complete
            store_tile(kvr, vvr);
            __syncthreads();           // tile jb+1 visible
        }
    }

    // normalize + write y (fp16, single plane)
    const float i0 = 1.f / l0;
    const float i1 = 1.f / l1;
#pragma unroll
    for (int j = 0; j < 8; j++) {
        const int col = 8 * j + 2 * c;
        *reinterpret_cast<uint32_t*>(Yg + base + (size_t)r0 * N_EMBD + col) =
            pack_h(O[j][0] * i0, O[j][1] * i0);
        *reinterpret_cast<uint32_t*>(Yg + base + (size_t)r1 * N_EMBD + col) =
            pack_h(O[j][2] * i1, O[j][3] * i1);
    }
}

// ---------------------------------------------------------------------------
// Launcher. Inputs: x,Wq,bq,Wk,bk,Wv,bv,Wo,bo,Wc   (6 launches total)
// ---------------------------------------------------------------------------
extern "C" void kernel_launch(void* const* d_in, const int* in_sizes, int n_in,
                              void* d_out, int out_size)
{
    const float* x  = (const float*)d_in[0];
    const float* Wq = (const float*)d_in[1];
    const float* bq = (const float*)d_in[2];
    const float* Wk = (const float*)d_in[3];
    const float* bk = (const float*)d_in[4];
    const float* Wv = (const float*)d_in[5];
    const float* bv = (const float*)d_in[6];
    const float* Wo = (const float*)d_in[7];
    const float* bo = (const float*)d_in[8];
    const float* Wc = (const float*)d_in[9];
    float* out = (float*)d_out;

    float *pWqc, *pbqc;
    __half *pqkv, *pxh, *pxl, *pys, *pwt;
    cudaGetSymbolAddress((void**)&pWqc, g_Wqc);
    cudaGetSymbolAddress((void**)&pbqc, g_bqc);
    cudaGetSymbolAddress((void**)&pqkv, g_qkv);
    cudaGetSymbolAddress((void**)&pxh,  g_xs_hi);
    cudaGetSymbolAddress((void**)&pxl,  g_xs_lo);
    cudaGetSymbolAddress((void**)&pys,  g_ys);
    cudaGetSymbolAddress((void**)&pwt,  g_wt);

    const size_t MN = (size_t)MROWS * N_EMBD;

    cudaFuncSetAttribute(gemm_qkv_mma,
                         cudaFuncAttributeMaxDynamicSharedMemorySize, GEMM_SMEM);
    cudaFuncSetAttribute(gemm_out_mma,
                         cudaFuncAttributeMaxDynamicSharedMemorySize, GEMM_SMEM);

    // 1. Wqc build
    build_wqc<<<4096, 256>>>(Wq, Wc, bq, pWqc, pbqc);

    // 2. split x (fp16)
    const int n2x = MROWS * N_EMBD / 2;
    split2h<<<(n2x + 255) / 256, 256>>>(x, (__half2*)pxh, (__half2*)pxl, n2x);

    // 3. transpose all weights to [N][K] fp16
    const dim3 tg(N_EMBD / 32, N_EMBD / 32, 4);
    tsplit_all<<<tg, dim3(32, 8)>>>(pWqc, Wk, Wv, Wo, pwt);

    // 4. QKV projection (q: 2-term, k/v: 1-term; fp16 outputs)
    const dim3 gq(N_EMBD / 128, MROWS / 128, 3);
    gemm_qkv_mma<<<gq, 256, GEMM_SMEM>>>(pxh, pxl, pbqc, bk, bv, pqkv);

    // 5. attention (single-MMA QK and PV; fp32 softmax)
    flash_mma<<<dim3(SEQ / 128, BATCH * N_HEADS), 256>>>(
        pqkv,                            // Q
        pqkv + MN,                       // K
        pqkv + 2 * MN,                   // V
        pys);

    // 6. output projection (1-term fp16)
    const dim3 gg(N_EMBD / 128, MROWS / 128);
    gemm_out_mma<<<gg, 256, GEMM_SMEM>>>(pys, bo, out);
}